// round 1
// baseline (speedup 1.0000x reference)
#include <cuda_runtime.h>
#include <cuda_bf16.h>
#include <cstdint>

// Problem constants
#define BB    256          // batch*windows
#define NN    343          // tokens per window
#define HH    6            // heads
#define DD    32           // head dim
#define CC    192          // channels
#define MM    (BB*NN)      // 87808 rows
#define NW    64           // windows in mask
#define NPAD  352          // 343 padded to mult of 32
#define QK_SCALE 0.17677669529663687f   // 32^-0.5

// ---------------- scratch (static device globals; no allocs) ----------------
__device__ float g_q [BB*HH*NN*DD];   // scaled Q, head-major  [bh][n][d]
__device__ float g_k [BB*HH*NN*DD];
__device__ float g_v [BB*HH*NN*DD];
__device__ float g_ao[MM*CC];         // attention output [b*343+n][c]
__device__ float g_rpb[HH*NN*NN];     // gathered bias [h][n][m]

// ---------------- GEMM: C[m,n] = A[m,:] . W[n,:] + bias[n] -----------------
// A: [M,192] row-major, W: [Nout,192] row-major (torch Linear weight)
// BM=128, BN=64, BK=16, 256 threads, 8x4 microtile. Shapes divide exactly.
// MODE 0: plain write to C (proj -> d_out)
// MODE 1: scale & scatter to g_q head-major
// MODE 2: split cols [0,192)->g_k, [192,384)->g_v head-major
template <int MODE>
__global__ void __launch_bounds__(256)
gemm_tn(const float* __restrict__ A, const float* __restrict__ W,
        const float* __restrict__ bias, float* __restrict__ C0,
        float* __restrict__ C1)
{
    __shared__ float As[16][132];
    __shared__ float Ws[16][68];

    const int m0 = blockIdx.x * 128;
    const int n0 = blockIdx.y * 64;
    const int tid = threadIdx.x;
    const int tx = tid & 15;        // -> 4 cols
    const int ty = tid >> 4;        // -> 8 rows

    float acc[8][4];
    #pragma unroll
    for (int i = 0; i < 8; i++)
        #pragma unroll
        for (int j = 0; j < 4; j++) acc[i][j] = 0.f;

    for (int k0 = 0; k0 < CC; k0 += 16) {
        // A tile: 128x16 = 512 float4, 2 per thread
        #pragma unroll
        for (int q = 0; q < 2; q++) {
            int f   = tid + q * 256;
            int row = f >> 2, kc = f & 3;
            float4 av = *(const float4*)(A + (size_t)(m0 + row) * CC + k0 + kc * 4);
            As[kc*4+0][row] = av.x; As[kc*4+1][row] = av.y;
            As[kc*4+2][row] = av.z; As[kc*4+3][row] = av.w;
        }
        // W tile: 64x16 = 256 float4, 1 per thread
        {
            int row = tid >> 2, kc = tid & 3;
            float4 wv = *(const float4*)(W + (size_t)(n0 + row) * CC + k0 + kc * 4);
            Ws[kc*4+0][row] = wv.x; Ws[kc*4+1][row] = wv.y;
            Ws[kc*4+2][row] = wv.z; Ws[kc*4+3][row] = wv.w;
        }
        __syncthreads();
        #pragma unroll
        for (int kk = 0; kk < 16; kk++) {
            float a[8], b[4];
            #pragma unroll
            for (int i = 0; i < 8; i++) a[i] = As[kk][ty*8 + i];
            #pragma unroll
            for (int j = 0; j < 4; j++) b[j] = Ws[kk][tx*4 + j];
            #pragma unroll
            for (int i = 0; i < 8; i++)
                #pragma unroll
                for (int j = 0; j < 4; j++)
                    acc[i][j] += a[i] * b[j];
        }
        __syncthreads();
    }

    // epilogue
    #pragma unroll
    for (int i = 0; i < 8; i++) {
        int m = m0 + ty*8 + i;
        #pragma unroll
        for (int j = 0; j < 4; j++) {
            int n = n0 + tx*4 + j;
            float v = acc[i][j] + bias[n];
            if (MODE == 0) {
                C0[(size_t)m * CC + n] = v;
            } else if (MODE == 1) {
                int b_ = m / NN, nn = m - b_ * NN;
                int h  = n >> 5, dd = n & 31;
                C0[(((size_t)(b_*HH + h))*NN + nn)*DD + dd] = v * QK_SCALE;
            } else { // MODE 2
                int b_ = m / NN, nn = m - b_ * NN;
                if (n < CC) {
                    int h = n >> 5, dd = n & 31;
                    C0[(((size_t)(b_*HH + h))*NN + nn)*DD + dd] = v;
                } else {
                    int n2 = n - CC;
                    int h = n2 >> 5, dd = n2 & 31;
                    C1[(((size_t)(b_*HH + h))*NN + nn)*DD + dd] = v;
                }
            }
        }
    }
}

// ---------------- RPB gather: rpb[h][n][m] = table[rpi[n][m]][h] -----------
__global__ void rpb_gather(const float* __restrict__ table,
                           const int* __restrict__ rpi,
                           float* __restrict__ out)
{
    int idx = blockIdx.x * 256 + threadIdx.x;
    const int NM = NN * NN;
    if (idx < HH * NM) {
        int h   = idx / NM;
        int rem = idx - h * NM;
        out[idx] = table[rpi[rem] * HH + h];
    }
}

// ---------------- Attention: one CTA per (b,h) ------------------------------
// smem: Ks[352*33] Vs[352*33] sbuf[8 warps][2 rows][352] qb[8][2][32]
#define SM_KS   0
#define SM_VS   (NPAD*33)
#define SM_SB   (2*NPAD*33)
#define SM_QB   (2*NPAD*33 + 16*NPAD)
#define SM_TOT  (2*NPAD*33 + 16*NPAD + 512)   // floats

__global__ void __launch_bounds__(256)
attn_kernel(const float* __restrict__ q_s, const float* __restrict__ k_s,
            const float* __restrict__ v_s, const float* __restrict__ rpb,
            const float* __restrict__ mask, float* __restrict__ ao)
{
    extern __shared__ float sm[];
    float* Ks   = sm + SM_KS;
    float* Vs   = sm + SM_VS;
    float* sbuf = sm + SM_SB;
    float* qb   = sm + SM_QB;

    const int bh = blockIdx.x;
    const int b  = bh / HH, h = bh - b * HH;
    const int tid = threadIdx.x, w = tid >> 5, lane = tid & 31;

    // stage K,V (zero pad rows 343..351)
    const float* kbase = k_s + (size_t)bh * NN * DD;
    const float* vbase = v_s + (size_t)bh * NN * DD;
    for (int i = tid; i < NPAD * DD; i += 256) {
        int m = i >> 5, d = i & 31;
        float kv = 0.f, vv = 0.f;
        if (m < NN) { kv = kbase[m*DD + d]; vv = vbase[m*DD + d]; }
        Ks[m*33 + d] = kv;
        Vs[m*33 + d] = vv;
    }
    __syncthreads();

    const float* maskb = mask + (size_t)(b & (NW-1)) * NN * NN;
    const float* rpbb  = rpb  + (size_t)h * NN * NN;
    const float* qbase = q_s  + (size_t)bh * NN * DD;

    for (int r0 = w * 2; r0 < NN; r0 += 16) {
        const int r1 = r0 + 1;
        const bool has1 = (r1 < NN);

        qb[w*64 + lane]      = qbase[r0*DD + lane];
        qb[w*64 + 32 + lane] = has1 ? qbase[r1*DD + lane] : 0.f;
        __syncwarp();

        float acc0[11], acc1[11];
        #pragma unroll
        for (int mi = 0; mi < 11; mi++) { acc0[mi] = 0.f; acc1[mi] = 0.f; }

        #pragma unroll 8
        for (int d = 0; d < DD; d++) {
            float q0 = qb[w*64 + d];
            float q1 = qb[w*64 + 32 + d];
            #pragma unroll
            for (int mi = 0; mi < 11; mi++) {
                float kv = Ks[(lane + (mi << 5))*33 + d];
                acc0[mi] += q0 * kv;
                acc1[mi] += q1 * kv;
            }
        }

        // bias + mask + row max
        float mx0 = -1e30f, mx1 = -1e30f;
        #pragma unroll
        for (int mi = 0; mi < 11; mi++) {
            int m = lane + (mi << 5);
            if (m < NN) {
                float bm0 = rpbb[r0*NN + m] + maskb[r0*NN + m];
                acc0[mi] += bm0;
                mx0 = fmaxf(mx0, acc0[mi]);
                if (has1) {
                    float bm1 = rpbb[r1*NN + m] + maskb[r1*NN + m];
                    acc1[mi] += bm1;
                    mx1 = fmaxf(mx1, acc1[mi]);
                }
            } else { acc0[mi] = -1e30f; acc1[mi] = -1e30f; }
        }
        #pragma unroll
        for (int o = 16; o; o >>= 1) {
            mx0 = fmaxf(mx0, __shfl_xor_sync(0xffffffffu, mx0, o));
            mx1 = fmaxf(mx1, __shfl_xor_sync(0xffffffffu, mx1, o));
        }

        float sum0 = 0.f, sum1 = 0.f;
        #pragma unroll
        for (int mi = 0; mi < 11; mi++) {
            int m = lane + (mi << 5);
            float e0 = (m < NN) ? __expf(acc0[mi] - mx0) : 0.f;
            float e1 = (m < NN && has1) ? __expf(acc1[mi] - mx1) : 0.f;
            sum0 += e0; sum1 += e1;
            sbuf[(w*2 + 0)*NPAD + m] = e0;
            sbuf[(w*2 + 1)*NPAD + m] = e1;
        }
        #pragma unroll
        for (int o = 16; o; o >>= 1) {
            sum0 += __shfl_xor_sync(0xffffffffu, sum0, o);
            sum1 += __shfl_xor_sync(0xffffffffu, sum1, o);
        }
        float inv0 = 1.f / sum0;
        float inv1 = has1 ? 1.f / sum1 : 0.f;
        __syncwarp();

        // PV: lane owns output dim d = lane
        float o0 = 0.f, o1 = 0.f;
        const float4* p0 = (const float4*)(sbuf + (size_t)(w*2 + 0)*NPAD);
        const float4* p1 = (const float4*)(sbuf + (size_t)(w*2 + 1)*NPAD);
        #pragma unroll 4
        for (int mq = 0; mq < NPAD/4; mq++) {
            float4 a = p0[mq];
            float4 c = p1[mq];
            int mb = mq * 4;
            float v0 = Vs[(mb + 0)*33 + lane];
            float v1 = Vs[(mb + 1)*33 + lane];
            float v2 = Vs[(mb + 2)*33 + lane];
            float v3 = Vs[(mb + 3)*33 + lane];
            o0 += a.x*v0 + a.y*v1 + a.z*v2 + a.w*v3;
            o1 += c.x*v0 + c.y*v1 + c.z*v2 + c.w*v3;
        }
        ao[((size_t)(b*NN + r0))*CC + h*DD + lane] = o0 * inv0;
        if (has1)
            ao[((size_t)(b*NN + r1))*CC + h*DD + lane] = o1 * inv1;
        __syncwarp();
    }
}

// ---------------- launch ----------------------------------------------------
extern "C" void kernel_launch(void* const* d_in, const int* in_sizes, int n_in,
                              void* d_out, int out_size)
{
    const float* x_q    = (const float*)d_in[0];
    const float* x_kv   = (const float*)d_in[1];
    const float* mask   = (const float*)d_in[2];
    const float* q_w    = (const float*)d_in[3];
    const float* q_b    = (const float*)d_in[4];
    const float* kv_w   = (const float*)d_in[5];
    const float* kv_b   = (const float*)d_in[6];
    const float* proj_w = (const float*)d_in[7];
    const float* proj_b = (const float*)d_in[8];
    const float* rtab   = (const float*)d_in[9];
    const int*   rpi    = (const int*)  d_in[10];
    float* out = (float*)d_out;

    float *qs, *ks, *vs, *ao, *rpb;
    cudaGetSymbolAddress((void**)&qs,  g_q);
    cudaGetSymbolAddress((void**)&ks,  g_k);
    cudaGetSymbolAddress((void**)&vs,  g_v);
    cudaGetSymbolAddress((void**)&ao,  g_ao);
    cudaGetSymbolAddress((void**)&rpb, g_rpb);

    const int smem_bytes = SM_TOT * 4;
    cudaFuncSetAttribute(attn_kernel,
                         cudaFuncAttributeMaxDynamicSharedMemorySize, smem_bytes);

    // Q projection (+scale, head-major scatter)
    gemm_tn<1><<<dim3(MM/128, CC/64), 256>>>(x_q, q_w, q_b, qs, nullptr);
    // KV projection (split into K/V head-major)
    gemm_tn<2><<<dim3(MM/128, (2*CC)/64), 256>>>(x_kv, kv_w, kv_b, ks, vs);
    // RPB gather
    {
        int tot = HH * NN * NN;
        rpb_gather<<<(tot + 255)/256, 256>>>(rtab, rpi, rpb);
    }
    // fused attention
    attn_kernel<<<BB*HH, 256, smem_bytes>>>(qs, ks, vs, rpb, mask, ao);
    // output projection -> d_out
    gemm_tn<0><<<dim3(MM/128, CC/64), 256>>>(ao, proj_w, proj_b, out, nullptr);
}

// round 3
// speedup vs baseline: 1.1804x; 1.1804x over previous
#include <cuda_runtime.h>
#include <cuda_bf16.h>
#include <cstdint>

// Problem constants
#define BB    256          // batch*windows
#define NN    343          // tokens per window
#define HH    6            // heads
#define DD    32           // head dim
#define CC    192          // channels
#define MM    (BB*NN)      // 87808 rows
#define NW    64           // windows in mask
#define NPAD  352          // 343 padded to mult of 32
#define QK_SCALE 0.17677669529663687f   // 32^-0.5

// ---------------- scratch (static device globals; no allocs) ----------------
__device__ float g_q [BB*HH*NN*DD];   // scaled Q, head-major  [bh][n][d]
__device__ float g_k [BB*HH*NN*DD];
__device__ float g_v [BB*HH*NN*DD];
__device__ float g_ao[MM*CC];         // attention output [b*343+n][c]
__device__ float g_rpb[HH*NN*NN];     // gathered bias [h][n][m]

// ---------------- GEMM: C[m,n] = A[m,:] . W[n,:] + bias[n] -----------------
// (unchanged from R1 — measured at fp32 SIMT roofline already)
template <int MODE>
__global__ void __launch_bounds__(256)
gemm_tn(const float* __restrict__ A, const float* __restrict__ W,
        const float* __restrict__ bias, float* __restrict__ C0,
        float* __restrict__ C1)
{
    __shared__ float As[16][132];
    __shared__ float Ws[16][68];

    const int m0 = blockIdx.x * 128;
    const int n0 = blockIdx.y * 64;
    const int tid = threadIdx.x;
    const int tx = tid & 15;        // -> 4 cols
    const int ty = tid >> 4;        // -> 8 rows

    float acc[8][4];
    #pragma unroll
    for (int i = 0; i < 8; i++)
        #pragma unroll
        for (int j = 0; j < 4; j++) acc[i][j] = 0.f;

    for (int k0 = 0; k0 < CC; k0 += 16) {
        #pragma unroll
        for (int q = 0; q < 2; q++) {
            int f   = tid + q * 256;
            int row = f >> 2, kc = f & 3;
            float4 av = *(const float4*)(A + (size_t)(m0 + row) * CC + k0 + kc * 4);
            As[kc*4+0][row] = av.x; As[kc*4+1][row] = av.y;
            As[kc*4+2][row] = av.z; As[kc*4+3][row] = av.w;
        }
        {
            int row = tid >> 2, kc = tid & 3;
            float4 wv = *(const float4*)(W + (size_t)(n0 + row) * CC + k0 + kc * 4);
            Ws[kc*4+0][row] = wv.x; Ws[kc*4+1][row] = wv.y;
            Ws[kc*4+2][row] = wv.z; Ws[kc*4+3][row] = wv.w;
        }
        __syncthreads();
        #pragma unroll
        for (int kk = 0; kk < 16; kk++) {
            float a[8], b[4];
            #pragma unroll
            for (int i = 0; i < 8; i++) a[i] = As[kk][ty*8 + i];
            #pragma unroll
            for (int j = 0; j < 4; j++) b[j] = Ws[kk][tx*4 + j];
            #pragma unroll
            for (int i = 0; i < 8; i++)
                #pragma unroll
                for (int j = 0; j < 4; j++)
                    acc[i][j] += a[i] * b[j];
        }
        __syncthreads();
    }

    #pragma unroll
    for (int i = 0; i < 8; i++) {
        int m = m0 + ty*8 + i;
        #pragma unroll
        for (int j = 0; j < 4; j++) {
            int n = n0 + tx*4 + j;
            float v = acc[i][j] + bias[n];
            if (MODE == 0) {
                C0[(size_t)m * CC + n] = v;
            } else if (MODE == 1) {
                int b_ = m / NN, nn = m - b_ * NN;
                int h  = n >> 5, dd = n & 31;
                C0[(((size_t)(b_*HH + h))*NN + nn)*DD + dd] = v * QK_SCALE;
            } else { // MODE 2
                int b_ = m / NN, nn = m - b_ * NN;
                if (n < CC) {
                    int h = n >> 5, dd = n & 31;
                    C0[(((size_t)(b_*HH + h))*NN + nn)*DD + dd] = v;
                } else {
                    int n2 = n - CC;
                    int h = n2 >> 5, dd = n2 & 31;
                    C1[(((size_t)(b_*HH + h))*NN + nn)*DD + dd] = v;
                }
            }
        }
    }
}

// ---------------- RPB gather: rpb[h][n][m] = table[rpi[n][m]][h] -----------
__global__ void rpb_gather(const float* __restrict__ table,
                           const int* __restrict__ rpi,
                           float* __restrict__ out)
{
    int idx = blockIdx.x * 256 + threadIdx.x;
    const int NM = NN * NN;
    if (idx < HH * NM) {
        int h   = idx / NM;
        int rem = idx - h * NM;
        out[idx] = table[rpi[rem] * HH + h];
    }
}

// ---------------- Attention: one CTA per (b,h), 512 threads -----------------
// smem: Ks[352*33] Vs[352*33] sbuf[16 warps][4 rows][352] qb[16][4][32]
#define SM_KS   0
#define SM_VS   (NPAD*33)
#define SM_SB   (2*NPAD*33)
#define SM_QB   (2*NPAD*33 + 64*NPAD)
#define SM_TOT  (2*NPAD*33 + 64*NPAD + 2048)   // 47808 floats = 191232 B

__global__ void __launch_bounds__(512)
attn_kernel(const float* __restrict__ q_s, const float* __restrict__ k_s,
            const float* __restrict__ v_s, const float* __restrict__ rpb,
            const float* __restrict__ mask, float* __restrict__ ao)
{
    extern __shared__ float sm[];
    float* Ks   = sm + SM_KS;
    float* Vs   = sm + SM_VS;
    float* sbuf = sm + SM_SB;
    float* qb   = sm + SM_QB;

    const int bh = blockIdx.x;
    const int b  = bh / HH, h = bh - b * HH;
    const int tid = threadIdx.x, w = tid >> 5, lane = tid & 31;

    // stage K,V (zero pad rows 343..351); stride 33 -> conflict-free in QK
    const float* kbase = k_s + (size_t)bh * NN * DD;
    const float* vbase = v_s + (size_t)bh * NN * DD;
    for (int i = tid; i < NPAD * DD; i += 512) {
        int m = i >> 5, d = i & 31;
        float kv = 0.f, vv = 0.f;
        if (m < NN) { kv = kbase[m*DD + d]; vv = vbase[m*DD + d]; }
        Ks[m*33 + d] = kv;
        Vs[m*33 + d] = vv;
    }
    __syncthreads();

    const float* maskb = mask + (size_t)(b & (NW-1)) * NN * NN;
    const float* rpbb  = rpb  + (size_t)h * NN * NN;
    const float* qbase = q_s  + (size_t)bh * NN * DD;

    for (int r0 = w * 4; r0 < NN; r0 += 64) {
        __syncwarp();
        // stage 4 q rows for this warp (zero-pad invalid rows)
        #pragma unroll
        for (int rr = 0; rr < 4; rr++) {
            int r = r0 + rr;
            qb[(w*4 + rr)*32 + lane] = (r < NN) ? qbase[r*DD + lane] : 0.f;
        }
        __syncwarp();

        // ---- QK^T: 4 rows x 11 m-chunks ----
        float acc[4][11];
        #pragma unroll
        for (int rr = 0; rr < 4; rr++)
            #pragma unroll
            for (int mi = 0; mi < 11; mi++) acc[rr][mi] = 0.f;

        const float4* qv4 = (const float4*)(qb + w*128);
        #pragma unroll
        for (int d4 = 0; d4 < 8; d4++) {
            float4 q0 = qv4[0*8 + d4];
            float4 q1 = qv4[1*8 + d4];
            float4 q2 = qv4[2*8 + d4];
            float4 q3 = qv4[3*8 + d4];
            #pragma unroll
            for (int mi = 0; mi < 11; mi++) {
                const float* kp = Ks + (lane + (mi << 5))*33 + (d4 << 2);
                float k0 = kp[0], k1 = kp[1], k2 = kp[2], k3 = kp[3];
                acc[0][mi] += q0.x*k0 + q0.y*k1 + q0.z*k2 + q0.w*k3;
                acc[1][mi] += q1.x*k0 + q1.y*k1 + q1.z*k2 + q1.w*k3;
                acc[2][mi] += q2.x*k0 + q2.y*k1 + q2.z*k2 + q2.w*k3;
                acc[3][mi] += q3.x*k0 + q3.y*k1 + q3.z*k2 + q3.w*k3;
            }
        }

        // ---- bias + mask + row max ----
        float mx[4] = {-1e30f, -1e30f, -1e30f, -1e30f};
        #pragma unroll
        for (int mi = 0; mi < 11; mi++) {
            int m = lane + (mi << 5);
            bool mv = (m < NN);
            #pragma unroll
            for (int rr = 0; rr < 4; rr++) {
                int r = r0 + rr;
                if (mv && r < NN) {
                    acc[rr][mi] += rpbb[(size_t)r*NN + m] + maskb[(size_t)r*NN + m];
                    mx[rr] = fmaxf(mx[rr], acc[rr][mi]);
                } else {
                    acc[rr][mi] = -1e30f;
                }
            }
        }
        #pragma unroll
        for (int rr = 0; rr < 4; rr++)
            #pragma unroll
            for (int o = 16; o; o >>= 1)
                mx[rr] = fmaxf(mx[rr], __shfl_xor_sync(0xffffffffu, mx[rr], o));

        // ---- exp, row sum, stage probabilities ----
        float sum[4] = {0.f, 0.f, 0.f, 0.f};
        #pragma unroll
        for (int mi = 0; mi < 11; mi++) {
            int m = lane + (mi << 5);
            #pragma unroll
            for (int rr = 0; rr < 4; rr++) {
                float e = __expf(acc[rr][mi] - mx[rr]);
                if (m >= NN) e = 0.f;
                sum[rr] += e;
                sbuf[(size_t)(w*4 + rr)*NPAD + m] = e;
            }
        }
        float inv[4];
        #pragma unroll
        for (int rr = 0; rr < 4; rr++) {
            #pragma unroll
            for (int o = 16; o; o >>= 1)
                sum[rr] += __shfl_xor_sync(0xffffffffu, sum[rr], o);
            inv[rr] = 1.f / sum[rr];
        }
        __syncwarp();

        // ---- PV: lane owns output dim d = lane; V load shared by 4 rows ----
        float out0 = 0.f, out1 = 0.f, out2 = 0.f, out3 = 0.f;
        const float4* p0 = (const float4*)(sbuf + (size_t)(w*4 + 0)*NPAD);
        const float4* p1 = (const float4*)(sbuf + (size_t)(w*4 + 1)*NPAD);
        const float4* p2 = (const float4*)(sbuf + (size_t)(w*4 + 2)*NPAD);
        const float4* p3 = (const float4*)(sbuf + (size_t)(w*4 + 3)*NPAD);
        #pragma unroll 4
        for (int mq = 0; mq < NPAD/4; mq++) {
            float4 a0 = p0[mq];
            float4 a1 = p1[mq];
            float4 a2 = p2[mq];
            float4 a3 = p3[mq];
            int mb = mq * 4;
            float v0 = Vs[(mb + 0)*33 + lane];
            float v1 = Vs[(mb + 1)*33 + lane];
            float v2 = Vs[(mb + 2)*33 + lane];
            float v3 = Vs[(mb + 3)*33 + lane];
            out0 += a0.x*v0 + a0.y*v1 + a0.z*v2 + a0.w*v3;
            out1 += a1.x*v0 + a1.y*v1 + a1.z*v2 + a1.w*v3;
            out2 += a2.x*v0 + a2.y*v1 + a2.z*v2 + a2.w*v3;
            out3 += a3.x*v0 + a3.y*v1 + a3.z*v2 + a3.w*v3;
        }
        float outs[4] = {out0, out1, out2, out3};
        #pragma unroll
        for (int rr = 0; rr < 4; rr++) {
            int r = r0 + rr;
            if (r < NN)
                ao[((size_t)(b*NN + r))*CC + h*DD + lane] = outs[rr] * inv[rr];
        }
    }
}

// ---------------- launch ----------------------------------------------------
extern "C" void kernel_launch(void* const* d_in, const int* in_sizes, int n_in,
                              void* d_out, int out_size)
{
    const float* x_q    = (const float*)d_in[0];
    const float* x_kv   = (const float*)d_in[1];
    const float* mask   = (const float*)d_in[2];
    const float* q_w    = (const float*)d_in[3];
    const float* q_b    = (const float*)d_in[4];
    const float* kv_w   = (const float*)d_in[5];
    const float* kv_b   = (const float*)d_in[6];
    const float* proj_w = (const float*)d_in[7];
    const float* proj_b = (const float*)d_in[8];
    const float* rtab   = (const float*)d_in[9];
    const int*   rpi    = (const int*)  d_in[10];
    float* out = (float*)d_out;

    float *qs, *ks, *vs, *ao, *rpb;
    cudaGetSymbolAddress((void**)&qs,  g_q);
    cudaGetSymbolAddress((void**)&ks,  g_k);
    cudaGetSymbolAddress((void**)&vs,  g_v);
    cudaGetSymbolAddress((void**)&ao,  g_ao);
    cudaGetSymbolAddress((void**)&rpb, g_rpb);

    const int smem_bytes = SM_TOT * 4;   // 191232 B
    cudaFuncSetAttribute(attn_kernel,
                         cudaFuncAttributeMaxDynamicSharedMemorySize, smem_bytes);

    // Q projection (+scale, head-major scatter)
    gemm_tn<1><<<dim3(MM/128, CC/64), 256>>>(x_q, q_w, q_b, qs, nullptr);
    // KV projection (split into K/V head-major)
    gemm_tn<2><<<dim3(MM/128, (2*CC)/64), 256>>>(x_kv, kv_w, kv_b, ks, vs);
    // RPB gather
    {
        int tot = HH * NN * NN;
        rpb_gather<<<(tot + 255)/256, 256>>>(rtab, rpi, rpb);
    }
    // fused attention
    attn_kernel<<<BB*HH, 512, smem_bytes>>>(qs, ks, vs, rpb, mask, ao);
    // output projection -> d_out
    gemm_tn<0><<<dim3(MM/128, CC/64), 256>>>(ao, proj_w, proj_b, out, nullptr);
}

// round 9
// speedup vs baseline: 1.3524x; 1.1457x over previous
#include <cuda_runtime.h>
#include <cuda_bf16.h>
#include <cstdint>

// Problem constants
#define BB    256
#define NN    343
#define HH    6
#define DD    32
#define CC    192
#define MM    (BB*NN)      // 87808 = 686*128
#define NW    64
#define NPAD  352
#define QK_SCALE 0.17677669529663687f

// ---------------- scratch -----------------------------------------------
__device__ float g_q [BB*HH*NN*DD];
__device__ float g_k [BB*HH*NN*DD];
__device__ float g_v [BB*HH*NN*DD];
__device__ float g_rpb[HH*NN*NN];
__device__ __nv_bfloat16 g_xqb [MM*384];   // [m][hi 0..191 | lo 192..383]
__device__ __nv_bfloat16 g_xkvb[MM*384];
__device__ __nv_bfloat16 g_aob [MM*384];
__device__ __nv_bfloat16 g_wcat[768*576];  // rows: q 0..191, kv 192..575, proj 576..767

__device__ __forceinline__ uint32_t smem_u32(const void* p) {
    uint32_t a;
    asm("{ .reg .u64 t; cvta.to.shared.u64 t, %1; cvt.u32.u64 %0, t; }" : "=r"(a) : "l"(p));
    return a;
}
#define LDMATRIX_X4(r0,r1,r2,r3, addr) \
    asm volatile("ldmatrix.sync.aligned.m8n8.x4.shared.b16 {%0,%1,%2,%3}, [%4];" \
        : "=r"(r0), "=r"(r1), "=r"(r2), "=r"(r3) : "r"(addr))
#define MMA_BF16(d0,d1,d2,d3, a0,a1,a2,a3, b0,b1) \
    asm volatile("mma.sync.aligned.m16n8k16.row.col.f32.bf16.bf16.f32 " \
        "{%0,%1,%2,%3}, {%4,%5,%6,%7}, {%8,%9}, {%0,%1,%2,%3};" \
        : "+f"(d0), "+f"(d1), "+f"(d2), "+f"(d3) \
        : "r"(a0), "r"(a1), "r"(a2), "r"(a3), "r"(b0), "r"(b1))

// ---------------- conversions -------------------------------------------
__global__ void aconv_kernel(const float* __restrict__ x, __nv_bfloat16* __restrict__ out)
{
    int idx = blockIdx.x * 256 + threadIdx.x;      // [0, MM*96)
    if (idx >= MM * 96) return;
    int m = idx / 96, w = idx % 96;
    float2 f = *(const float2*)(x + (size_t)m * CC + w * 2);
    __nv_bfloat16 h0 = __float2bfloat16_rn(f.x);
    __nv_bfloat16 h1 = __float2bfloat16_rn(f.y);
    __nv_bfloat162 hp(h0, h1);
    __nv_bfloat162 lp = __floats2bfloat162_rn(f.x - __bfloat162float(h0),
                                              f.y - __bfloat162float(h1));
    *(__nv_bfloat162*)(out + (size_t)m * 384 + w * 2)       = hp;
    *(__nv_bfloat162*)(out + (size_t)m * 384 + 192 + w * 2) = lp;
}

__global__ void wconv_kernel(const float* __restrict__ q_w,
                             const float* __restrict__ kv_w,
                             const float* __restrict__ proj_w,
                             __nv_bfloat16* __restrict__ wc)
{
    int idx = blockIdx.x * 256 + threadIdx.x;      // [0, 768*288)
    if (idx >= 768 * 288) return;
    int row = idx / 288, p = idx % 288;
    int kp = p * 2;                                 // 0..574 even
    const float* src; int r;
    if (row < 192)      { src = q_w;    r = row; }
    else if (row < 576) { src = kv_w;   r = row - 192; }
    else                { src = proj_w; r = row - 576; }
    int sc = (kp < 192) ? kp : ((kp < 384) ? kp - 192 : kp - 384);
    float f0 = src[(size_t)r * CC + sc];
    float f1 = src[(size_t)r * CC + sc + 1];
    __nv_bfloat16 h0 = __float2bfloat16_rn(f0);
    __nv_bfloat16 h1 = __float2bfloat16_rn(f1);
    __nv_bfloat162 v;
    if (kp < 384) v = __nv_bfloat162(h0, h1);
    else          v = __floats2bfloat162_rn(f0 - __bfloat162float(h0),
                                            f1 - __bfloat162float(h1));
    *(__nv_bfloat162*)(wc + (size_t)row * 576 + kp) = v;
}

// ---------------- HMMA GEMM ----------------------------------------------
// C[m,n] = sum_{k'=0..575} Acat[m][k'] * Wcat[n][k']  (+bias)
// Acat: [Ah|Al|Ah] (stored [Ah|Al], 384 cols). Wcat: [Bh|Bh|Bl] (576 cols).
// BM=128, BN=64, BK=64; 8 warps, warp tile 32x32 (2 m-tiles x 4 n-tiles).
// MODE 0: plain to C0 (proj->d_out). MODE 1: q scale+scatter. MODE 2: kv split.
#define AS_STRIDE 72
#define BS_STRIDE 72

template <int MODE>
__global__ void __launch_bounds__(256)
gemm_mma(const __nv_bfloat16* __restrict__ gA, const __nv_bfloat16* __restrict__ gW,
         const float* __restrict__ bias, float* __restrict__ C0, float* __restrict__ C1)
{
    __shared__ __nv_bfloat16 As[128 * AS_STRIDE];
    __shared__ __nv_bfloat16 Bs[64  * BS_STRIDE];

    const int tid = threadIdx.x, w = tid >> 5, lane = tid & 31;
    const int m0 = blockIdx.x * 128;
    const int nbase = blockIdx.y * 64;
    const int wm = (w & 3) * 32;     // warp m offset in tile
    const int wn = (w >> 2) * 32;    // warp n offset in tile

    // ldmatrix lane addressing (element offsets, k added later)
    const int a_row = lane & 15;               // 0..15
    const int a_koff = (lane >> 4) << 3;       // 0 or 8
    const int b_mat = lane >> 3;               // 0..3
    const int b_l   = lane & 7;
    const int b_nloc = (b_mat & 2) ? 8 : 0;    // +8 for mats 2,3
    const int b_koff = (b_mat & 1) ? 8 : 0;

    float d[2][4][4];
    #pragma unroll
    for (int mt = 0; mt < 2; mt++)
        #pragma unroll
        for (int nt = 0; nt < 4; nt++)
            #pragma unroll
            for (int j = 0; j < 4; j++) d[mt][nt][j] = 0.f;

    const uint32_t as_base = smem_u32(As);
    const uint32_t bs_base = smem_u32(Bs);

    for (int it = 0; it < 9; it++) {
        const int kp0 = it * 64;
        const int acol0 = (kp0 < 384) ? kp0 : kp0 - 384;
        // load A: 128 rows x 8 uint4
        #pragma unroll
        for (int q = 0; q < 4; q++) {
            int f = tid + q * 256;
            int row = f >> 3, cu = f & 7;
            uint4 v = *(const uint4*)(gA + (size_t)(m0 + row) * 384 + acol0 + cu * 8);
            *(uint4*)(As + row * AS_STRIDE + cu * 8) = v;
        }
        // load B: 64 rows x 8 uint4
        #pragma unroll
        for (int q = 0; q < 2; q++) {
            int f = tid + q * 256;
            int row = f >> 3, cu = f & 7;
            uint4 v = *(const uint4*)(gW + (size_t)(nbase + row) * 576 + kp0 + cu * 8);
            *(uint4*)(Bs + row * BS_STRIDE + cu * 8) = v;
        }
        __syncthreads();

        #pragma unroll
        for (int ks = 0; ks < 4; ks++) {
            const int k0 = ks * 16;
            uint32_t a[2][4], bb[2][4];
            #pragma unroll
            for (int mt = 0; mt < 2; mt++) {
                uint32_t addr = as_base +
                    ((wm + mt*16 + a_row) * AS_STRIDE + k0 + a_koff) * 2;
                LDMATRIX_X4(a[mt][0], a[mt][1], a[mt][2], a[mt][3], addr);
            }
            #pragma unroll
            for (int bt = 0; bt < 2; bt++) {
                uint32_t addr = bs_base +
                    ((wn + bt*16 + b_nloc + b_l) * BS_STRIDE + k0 + b_koff) * 2;
                LDMATRIX_X4(bb[bt][0], bb[bt][1], bb[bt][2], bb[bt][3], addr);
            }
            #pragma unroll
            for (int mt = 0; mt < 2; mt++) {
                #pragma unroll
                for (int nt = 0; nt < 4; nt++) {
                    uint32_t b0 = bb[nt >> 1][(nt & 1) * 2];
                    uint32_t b1 = bb[nt >> 1][(nt & 1) * 2 + 1];
                    MMA_BF16(d[mt][nt][0], d[mt][nt][1], d[mt][nt][2], d[mt][nt][3],
                             a[mt][0], a[mt][1], a[mt][2], a[mt][3], b0, b1);
                }
            }
        }
        __syncthreads();
    }

    // ---- epilogue ----
    const int g = lane >> 2, tg = lane & 3;
    #pragma unroll
    for (int mt = 0; mt < 2; mt++) {
        #pragma unroll
        for (int half = 0; half < 2; half++) {
            const int m = m0 + wm + mt * 16 + g + half * 8;
            const int b_ = m / NN, nn = m - b_ * NN;
            #pragma unroll
            for (int nt = 0; nt < 4; nt++) {
                const int n = nbase + wn + nt * 8 + tg * 2;
                float v0 = d[mt][nt][half * 2 + 0] + bias[n];
                float v1 = d[mt][nt][half * 2 + 1] + bias[n + 1];
                if (MODE == 0) {
                    *(float2*)(C0 + (size_t)m * CC + n) = make_float2(v0, v1);
                } else if (MODE == 1) {
                    int h = n >> 5, dd = n & 31;
                    *(float2*)(C0 + (((size_t)(b_*HH + h))*NN + nn)*DD + dd)
                        = make_float2(v0 * QK_SCALE, v1 * QK_SCALE);
                } else {
                    int h = n >> 5, dd = n & 31;
                    float* base = (h < HH)
                        ? (C0 + (((size_t)(b_*HH + h))*NN + nn)*DD + dd)
                        : (C1 + (((size_t)(b_*HH + (h - HH)))*NN + nn)*DD + dd);
                    *(float2*)base = make_float2(v0, v1);
                }
            }
        }
    }
}

// ---------------- RPB gather ---------------------------------------------
__global__ void rpb_gather(const float* __restrict__ table,
                           const int* __restrict__ rpi,
                           float* __restrict__ out)
{
    int idx = blockIdx.x * 256 + threadIdx.x;
    const int NM = NN * NN;
    if (idx < HH * NM) {
        int h   = idx / NM;
        int rem = idx - h * NM;
        out[idx] = table[rpi[rem] * HH + h];
    }
}

// ---------------- Attention (R3 compute; epilogue -> bf16 hi/lo) ----------
#define SM_KS   0
#define SM_VS   (NPAD*33)
#define SM_SB   (2*NPAD*33)
#define SM_QB   (2*NPAD*33 + 64*NPAD)
#define SM_TOT  (2*NPAD*33 + 64*NPAD + 2048)

__global__ void __launch_bounds__(512)
attn_kernel(const float* __restrict__ q_s, const float* __restrict__ k_s,
            const float* __restrict__ v_s, const float* __restrict__ rpb,
            const float* __restrict__ mask, __nv_bfloat16* __restrict__ aob)
{
    extern __shared__ float sm[];
    float* Ks   = sm + SM_KS;
    float* Vs   = sm + SM_VS;
    float* sbuf = sm + SM_SB;
    float* qb   = sm + SM_QB;

    const int bh = blockIdx.x;
    const int b  = bh / HH, h = bh - b * HH;
    const int tid = threadIdx.x, w = tid >> 5, lane = tid & 31;

    const float* kbase = k_s + (size_t)bh * NN * DD;
    const float* vbase = v_s + (size_t)bh * NN * DD;
    for (int i = tid; i < NPAD * DD; i += 512) {
        int m = i >> 5, d = i & 31;
        float kv = 0.f, vv = 0.f;
        if (m < NN) { kv = kbase[m*DD + d]; vv = vbase[m*DD + d]; }
        Ks[m*33 + d] = kv;
        Vs[m*33 + d] = vv;
    }
    __syncthreads();

    const float* maskb = mask + (size_t)(b & (NW-1)) * NN * NN;
    const float* rpbb  = rpb  + (size_t)h * NN * NN;
    const float* qbase = q_s  + (size_t)bh * NN * DD;

    for (int r0 = w * 4; r0 < NN; r0 += 64) {
        __syncwarp();
        #pragma unroll
        for (int rr = 0; rr < 4; rr++) {
            int r = r0 + rr;
            qb[(w*4 + rr)*32 + lane] = (r < NN) ? qbase[r*DD + lane] : 0.f;
        }
        __syncwarp();

        float acc[4][11];
        #pragma unroll
        for (int rr = 0; rr < 4; rr++)
            #pragma unroll
            for (int mi = 0; mi < 11; mi++) acc[rr][mi] = 0.f;

        const float4* qv4 = (const float4*)(qb + w*128);
        #pragma unroll
        for (int d4 = 0; d4 < 8; d4++) {
            float4 q0 = qv4[0*8 + d4];
            float4 q1 = qv4[1*8 + d4];
            float4 q2 = qv4[2*8 + d4];
            float4 q3 = qv4[3*8 + d4];
            #pragma unroll
            for (int mi = 0; mi < 11; mi++) {
                const float* kp = Ks + (lane + (mi << 5))*33 + (d4 << 2);
                float k0 = kp[0], k1 = kp[1], k2 = kp[2], k3 = kp[3];
                acc[0][mi] += q0.x*k0 + q0.y*k1 + q0.z*k2 + q0.w*k3;
                acc[1][mi] += q1.x*k0 + q1.y*k1 + q1.z*k2 + q1.w*k3;
                acc[2][mi] += q2.x*k0 + q2.y*k1 + q2.z*k2 + q2.w*k3;
                acc[3][mi] += q3.x*k0 + q3.y*k1 + q3.z*k2 + q3.w*k3;
            }
        }

        float mx[4] = {-1e30f, -1e30f, -1e30f, -1e30f};
        #pragma unroll
        for (int mi = 0; mi < 11; mi++) {
            int m = lane + (mi << 5);
            bool mv = (m < NN);
            #pragma unroll
            for (int rr = 0; rr < 4; rr++) {
                int r = r0 + rr;
                if (mv && r < NN) {
                    acc[rr][mi] += rpbb[(size_t)r*NN + m] + maskb[(size_t)r*NN + m];
                    mx[rr] = fmaxf(mx[rr], acc[rr][mi]);
                } else {
                    acc[rr][mi] = -1e30f;
                }
            }
        }
        #pragma unroll
        for (int rr = 0; rr < 4; rr++)
            #pragma unroll
            for (int o = 16; o; o >>= 1)
                mx[rr] = fmaxf(mx[rr], __shfl_xor_sync(0xffffffffu, mx[rr], o));

        float sum[4] = {0.f, 0.f, 0.f, 0.f};
        #pragma unroll
        for (int mi = 0; mi < 11; mi++) {
            int m = lane + (mi << 5);
            #pragma unroll
            for (int rr = 0; rr < 4; rr++) {
                float e = __expf(acc[rr][mi] - mx[rr]);
                if (m >= NN) e = 0.f;
                sum[rr] += e;
                sbuf[(size_t)(w*4 + rr)*NPAD + m] = e;
            }
        }
        float inv[4];
        #pragma unroll
        for (int rr = 0; rr < 4; rr++) {
            #pragma unroll
            for (int o = 16; o; o >>= 1)
                sum[rr] += __shfl_xor_sync(0xffffffffu, sum[rr], o);
            inv[rr] = 1.f / sum[rr];
        }
        __syncwarp();

        float out0 = 0.f, out1 = 0.f, out2 = 0.f, out3 = 0.f;
        const float4* p0 = (const float4*)(sbuf + (size_t)(w*4 + 0)*NPAD);
        const float4* p1 = (const float4*)(sbuf + (size_t)(w*4 + 1)*NPAD);
        const float4* p2 = (const float4*)(sbuf + (size_t)(w*4 + 2)*NPAD);
        const float4* p3 = (const float4*)(sbuf + (size_t)(w*4 + 3)*NPAD);
        #pragma unroll 4
        for (int mq = 0; mq < NPAD/4; mq++) {
            float4 a0 = p0[mq];
            float4 a1 = p1[mq];
            float4 a2 = p2[mq];
            float4 a3 = p3[mq];
            int mb = mq * 4;
            float v0 = Vs[(mb + 0)*33 + lane];
            float v1 = Vs[(mb + 1)*33 + lane];
            float v2 = Vs[(mb + 2)*33 + lane];
            float v3 = Vs[(mb + 3)*33 + lane];
            out0 += a0.x*v0 + a0.y*v1 + a0.z*v2 + a0.w*v3;
            out1 += a1.x*v0 + a1.y*v1 + a1.z*v2 + a1.w*v3;
            out2 += a2.x*v0 + a2.y*v1 + a2.z*v2 + a2.w*v3;
            out3 += a3.x*v0 + a3.y*v1 + a3.z*v2 + a3.w*v3;
        }
        float outs[4] = {out0, out1, out2, out3};
        #pragma unroll
        for (int rr = 0; rr < 4; rr++) {
            int r = r0 + rr;
            if (r < NN) {
                float f = outs[rr] * inv[rr];
                size_t m = (size_t)(b*NN + r);
                __nv_bfloat16 hi = __float2bfloat16_rn(f);
                aob[m*384 + h*DD + lane] = hi;
                aob[m*384 + 192 + h*DD + lane] =
                    __float2bfloat16_rn(f - __bfloat162float(hi));
            }
        }
    }
}

// ---------------- launch --------------------------------------------------
extern "C" void kernel_launch(void* const* d_in, const int* in_sizes, int n_in,
                              void* d_out, int out_size)
{
    const float* x_q    = (const float*)d_in[0];
    const float* x_kv   = (const float*)d_in[1];
    const float* mask   = (const float*)d_in[2];
    const float* q_w    = (const float*)d_in[3];
    const float* q_b    = (const float*)d_in[4];
    const float* kv_w   = (const float*)d_in[5];
    const float* kv_b   = (const float*)d_in[6];
    const float* proj_w = (const float*)d_in[7];
    const float* proj_b = (const float*)d_in[8];
    const float* rtab   = (const float*)d_in[9];
    const int*   rpi    = (const int*)  d_in[10];
    float* out = (float*)d_out;

    float *qs, *ks, *vs, *rpb;
    __nv_bfloat16 *xqb, *xkvb, *aob, *wc;
    cudaGetSymbolAddress((void**)&qs,   g_q);
    cudaGetSymbolAddress((void**)&ks,   g_k);
    cudaGetSymbolAddress((void**)&vs,   g_v);
    cudaGetSymbolAddress((void**)&rpb,  g_rpb);
    cudaGetSymbolAddress((void**)&xqb,  g_xqb);
    cudaGetSymbolAddress((void**)&xkvb, g_xkvb);
    cudaGetSymbolAddress((void**)&aob,  g_aob);
    cudaGetSymbolAddress((void**)&wc,   g_wcat);

    const int attn_smem = SM_TOT * 4;
    cudaFuncSetAttribute(attn_kernel, cudaFuncAttributeMaxDynamicSharedMemorySize, attn_smem);

    // conversions
    aconv_kernel<<<(MM*96 + 255)/256, 256>>>(x_q,  xqb);
    aconv_kernel<<<(MM*96 + 255)/256, 256>>>(x_kv, xkvb);
    wconv_kernel<<<(768*288 + 255)/256, 256>>>(q_w, kv_w, proj_w, wc);
    // Q projection (+scale, head-major scatter)
    gemm_mma<1><<<dim3(MM/128, 3), 256>>>(xqb, wc, q_b, qs, nullptr);
    // KV projection (split K/V head-major)
    gemm_mma<2><<<dim3(MM/128, 6), 256>>>(xkvb, wc + (size_t)192*576, kv_b, ks, vs);
    // RPB gather
    rpb_gather<<<(HH*NN*NN + 255)/256, 256>>>(rtab, rpi, rpb);
    // fused attention (writes bf16 hi/lo ao)
    attn_kernel<<<BB*HH, 512, attn_smem>>>(qs, ks, vs, rpb, mask, aob);
    // output projection -> d_out
    gemm_mma<0><<<dim3(MM/128, 3), 256>>>(aob, wc + (size_t)576*576, proj_b, out, nullptr);
}

// round 11
// speedup vs baseline: 1.7231x; 1.2741x over previous
#include <cuda_runtime.h>
#include <cuda_bf16.h>
#include <cstdint>

// Problem constants
#define BB    256
#define NN    343
#define HH    6
#define DD    32
#define CC    192
#define MM    (BB*NN)      // 87808 = 686*128
#define NW    64
#define QK_SCALE 0.17677669529663687f
#define BSTRIDE 344        // padded row stride for bias tables (4B-aligned rows)

// ---------------- scratch -----------------------------------------------
__device__ __nv_bfloat16 g_xqb [MM*384];   // GEMM A: [m][hi 0..191 | lo 192..383]
__device__ __nv_bfloat16 g_xkvb[MM*384];
__device__ __nv_bfloat16 g_aob [MM*384];
__device__ __nv_bfloat16 g_wcat[768*576];  // rows: q 0..191, kv 192..575, proj 576..767
__device__ __nv_bfloat16 g_qb [BB*HH*NN*64];   // [bh][n][hi 0..31 | lo 32..63]
__device__ __nv_bfloat16 g_kb [BB*HH*NN*64];
__device__ __nv_bfloat16 g_vb [BB*HH*NN*64];
__device__ __nv_bfloat16 g_rpbh [HH*NN*BSTRIDE + 512];   // bf16 bias [h][n][344]
__device__ __nv_bfloat16 g_maskh[NW*NN*BSTRIDE + 512];   // bf16 mask [w][n][344]

__device__ __forceinline__ uint32_t smem_u32(const void* p) {
    uint32_t a;
    asm("{ .reg .u64 t; cvta.to.shared.u64 t, %1; cvt.u32.u64 %0, t; }" : "=r"(a) : "l"(p));
    return a;
}
#define LDMATRIX_X4(r0,r1,r2,r3, addr) \
    asm volatile("ldmatrix.sync.aligned.m8n8.x4.shared.b16 {%0,%1,%2,%3}, [%4];" \
        : "=r"(r0), "=r"(r1), "=r"(r2), "=r"(r3) : "r"(addr))
#define LDMATRIX_X4_T(r0,r1,r2,r3, addr) \
    asm volatile("ldmatrix.sync.aligned.m8n8.x4.trans.shared.b16 {%0,%1,%2,%3}, [%4];" \
        : "=r"(r0), "=r"(r1), "=r"(r2), "=r"(r3) : "r"(addr))
#define MMA_BF16(d0,d1,d2,d3, a0,a1,a2,a3, b0,b1) \
    asm volatile("mma.sync.aligned.m16n8k16.row.col.f32.bf16.bf16.f32 " \
        "{%0,%1,%2,%3}, {%4,%5,%6,%7}, {%8,%9}, {%0,%1,%2,%3};" \
        : "+f"(d0), "+f"(d1), "+f"(d2), "+f"(d3) \
        : "r"(a0), "r"(a1), "r"(a2), "r"(a3), "r"(b0), "r"(b1))

__device__ __forceinline__ uint32_t packbf2(float x, float y) {
    __nv_bfloat162 t = __floats2bfloat162_rn(x, y);
    return *reinterpret_cast<uint32_t*>(&t);
}

// ---------------- conversions -------------------------------------------
__global__ void aconv_kernel(const float* __restrict__ x, __nv_bfloat16* __restrict__ out)
{
    int idx = blockIdx.x * 256 + threadIdx.x;      // [0, MM*96)
    if (idx >= MM * 96) return;
    int m = idx / 96, w = idx % 96;
    float2 f = *(const float2*)(x + (size_t)m * CC + w * 2);
    __nv_bfloat16 h0 = __float2bfloat16_rn(f.x);
    __nv_bfloat16 h1 = __float2bfloat16_rn(f.y);
    __nv_bfloat162 hp(h0, h1);
    __nv_bfloat162 lp = __floats2bfloat162_rn(f.x - __bfloat162float(h0),
                                              f.y - __bfloat162float(h1));
    *(__nv_bfloat162*)(out + (size_t)m * 384 + w * 2)       = hp;
    *(__nv_bfloat162*)(out + (size_t)m * 384 + 192 + w * 2) = lp;
}

__global__ void wconv_kernel(const float* __restrict__ q_w,
                             const float* __restrict__ kv_w,
                             const float* __restrict__ proj_w,
                             __nv_bfloat16* __restrict__ wc)
{
    int idx = blockIdx.x * 256 + threadIdx.x;      // [0, 768*288)
    if (idx >= 768 * 288) return;
    int row = idx / 288, p = idx % 288;
    int kp = p * 2;
    const float* src; int r;
    if (row < 192)      { src = q_w;    r = row; }
    else if (row < 576) { src = kv_w;   r = row - 192; }
    else                { src = proj_w; r = row - 576; }
    int sc = (kp < 192) ? kp : ((kp < 384) ? kp - 192 : kp - 384);
    float f0 = src[(size_t)r * CC + sc];
    float f1 = src[(size_t)r * CC + sc + 1];
    __nv_bfloat16 h0 = __float2bfloat16_rn(f0);
    __nv_bfloat16 h1 = __float2bfloat16_rn(f1);
    __nv_bfloat162 v;
    if (kp < 384) v = __nv_bfloat162(h0, h1);
    else          v = __floats2bfloat162_rn(f0 - __bfloat162float(h0),
                                            f1 - __bfloat162float(h1));
    *(__nv_bfloat162*)(wc + (size_t)row * 576 + kp) = v;
}

// rpb gather -> bf16 [h][n][344]
__global__ void rpb_gather_bf(const float* __restrict__ table,
                              const int* __restrict__ rpi,
                              __nv_bfloat16* __restrict__ out)
{
    int idx = blockIdx.x * 256 + threadIdx.x;
    const int NM = NN * NN;
    if (idx >= HH * NM) return;
    int h = idx / NM, rem = idx - h * NM;
    int n = rem / NN, m = rem - n * NN;
    out[((size_t)h * NN + n) * BSTRIDE + m] = __float2bfloat16_rn(table[rpi[rem] * HH + h]);
}

// mask -> bf16 [w][n][344]
__global__ void mconv_kernel(const float* __restrict__ mask, __nv_bfloat16* __restrict__ out)
{
    int idx = blockIdx.x * 256 + threadIdx.x;
    const int NM = NN * NN;
    if (idx >= NW * NM) return;
    int w = idx / NM, rem = idx - w * NM;
    int n = rem / NN, m = rem - n * NN;
    out[((size_t)w * NN + n) * BSTRIDE + m] = __float2bfloat16_rn(mask[idx]);
}

// ---------------- HMMA GEMM ----------------------------------------------
// MODE 0: fp32 to C0 (proj->d_out). MODE 1: q scale -> bf16 hi/lo B0.
// MODE 2: kv split -> bf16 hi/lo B0 (k), B1 (v).
#define AS_STRIDE 72
#define BS_STRIDE 72

template <int MODE>
__global__ void __launch_bounds__(256)
gemm_mma(const __nv_bfloat16* __restrict__ gA, const __nv_bfloat16* __restrict__ gW,
         const float* __restrict__ bias, float* __restrict__ C0,
         __nv_bfloat16* __restrict__ B0, __nv_bfloat16* __restrict__ B1)
{
    __shared__ __nv_bfloat16 As[128 * AS_STRIDE];
    __shared__ __nv_bfloat16 Bs[64  * BS_STRIDE];

    const int tid = threadIdx.x, w = tid >> 5, lane = tid & 31;
    const int m0 = blockIdx.x * 128;
    const int nbase = blockIdx.y * 64;
    const int wm = (w & 3) * 32;
    const int wn = (w >> 2) * 32;

    const int a_row = lane & 15;
    const int a_koff = (lane >> 4) << 3;
    const int b_l   = lane & 7;
    const int b_koff = ((lane >> 3) & 1) * 8;
    const int b_nloc = (lane >> 4) * 8;

    float d[2][4][4];
    #pragma unroll
    for (int mt = 0; mt < 2; mt++)
        #pragma unroll
        for (int nt = 0; nt < 4; nt++)
            #pragma unroll
            for (int j = 0; j < 4; j++) d[mt][nt][j] = 0.f;

    const uint32_t as_base = smem_u32(As);
    const uint32_t bs_base = smem_u32(Bs);

    for (int it = 0; it < 9; it++) {
        const int kp0 = it * 64;
        const int acol0 = (kp0 < 384) ? kp0 : kp0 - 384;
        #pragma unroll
        for (int q = 0; q < 4; q++) {
            int f = tid + q * 256;
            int row = f >> 3, cu = f & 7;
            uint4 v = *(const uint4*)(gA + (size_t)(m0 + row) * 384 + acol0 + cu * 8);
            *(uint4*)(As + row * AS_STRIDE + cu * 8) = v;
        }
        #pragma unroll
        for (int q = 0; q < 2; q++) {
            int f = tid + q * 256;
            int row = f >> 3, cu = f & 7;
            uint4 v = *(const uint4*)(gW + (size_t)(nbase + row) * 576 + kp0 + cu * 8);
            *(uint4*)(Bs + row * BS_STRIDE + cu * 8) = v;
        }
        __syncthreads();

        #pragma unroll
        for (int ks = 0; ks < 4; ks++) {
            const int k0 = ks * 16;
            uint32_t a[2][4], bb[2][4];
            #pragma unroll
            for (int mt = 0; mt < 2; mt++) {
                uint32_t addr = as_base + ((wm + mt*16 + a_row) * AS_STRIDE + k0 + a_koff) * 2;
                LDMATRIX_X4(a[mt][0], a[mt][1], a[mt][2], a[mt][3], addr);
            }
            #pragma unroll
            for (int bt = 0; bt < 2; bt++) {
                uint32_t addr = bs_base + ((wn + bt*16 + b_nloc + b_l) * BS_STRIDE + k0 + b_koff) * 2;
                LDMATRIX_X4(bb[bt][0], bb[bt][1], bb[bt][2], bb[bt][3], addr);
            }
            #pragma unroll
            for (int mt = 0; mt < 2; mt++) {
                #pragma unroll
                for (int nt = 0; nt < 4; nt++) {
                    uint32_t b0 = bb[nt >> 1][(nt & 1) * 2];
                    uint32_t b1 = bb[nt >> 1][(nt & 1) * 2 + 1];
                    MMA_BF16(d[mt][nt][0], d[mt][nt][1], d[mt][nt][2], d[mt][nt][3],
                             a[mt][0], a[mt][1], a[mt][2], a[mt][3], b0, b1);
                }
            }
        }
        __syncthreads();
    }

    const int g = lane >> 2, tg = lane & 3;
    #pragma unroll
    for (int mt = 0; mt < 2; mt++) {
        #pragma unroll
        for (int half = 0; half < 2; half++) {
            const int m = m0 + wm + mt * 16 + g + half * 8;
            const int b_ = m / NN, nn = m - b_ * NN;
            #pragma unroll
            for (int nt = 0; nt < 4; nt++) {
                const int n = nbase + wn + nt * 8 + tg * 2;
                float v0 = d[mt][nt][half * 2 + 0] + bias[n];
                float v1 = d[mt][nt][half * 2 + 1] + bias[n + 1];
                if (MODE == 0) {
                    *(float2*)(C0 + (size_t)m * CC + n) = make_float2(v0, v1);
                } else if (MODE == 1) {
                    int h = n >> 5, dd = n & 31;
                    float s0 = v0 * QK_SCALE, s1 = v1 * QK_SCALE;
                    __nv_bfloat16 h0 = __float2bfloat16_rn(s0);
                    __nv_bfloat16 h1 = __float2bfloat16_rn(s1);
                    __nv_bfloat16* dst = B0 + (((size_t)(b_*HH + h))*NN + nn)*64 + dd;
                    *(__nv_bfloat162*)dst = __nv_bfloat162(h0, h1);
                    *(__nv_bfloat162*)(dst + 32) =
                        __floats2bfloat162_rn(s0 - __bfloat162float(h0), s1 - __bfloat162float(h1));
                } else {
                    int h = n >> 5, dd = n & 31;
                    __nv_bfloat16* dst = (h < HH)
                        ? (B0 + (((size_t)(b_*HH + h))*NN + nn)*64 + dd)
                        : (B1 + (((size_t)(b_*HH + (h - HH)))*NN + nn)*64 + dd);
                    __nv_bfloat16 h0 = __float2bfloat16_rn(v0);
                    __nv_bfloat16 h1 = __float2bfloat16_rn(v1);
                    *(__nv_bfloat162*)dst = __nv_bfloat162(h0, h1);
                    *(__nv_bfloat162*)(dst + 32) =
                        __floats2bfloat162_rn(v0 - __bfloat162float(h0), v1 - __bfloat162float(h1));
                }
            }
        }
    }
}

// ---------------- HMMA flash attention -----------------------------------
// CTA: (bh, qtile of 128 rows), 8 warps x 16 rows. K/V/Q in smem bf16 hi|lo.
#define KVS 72
#define ATTN_SMEM ((2*352*KVS + 128*KVS) * 2)   // 119808 B

__global__ void __launch_bounds__(256)
attn_mma(const __nv_bfloat16* __restrict__ qb, const __nv_bfloat16* __restrict__ kb,
         const __nv_bfloat16* __restrict__ vb, const __nv_bfloat16* __restrict__ rpbh,
         const __nv_bfloat16* __restrict__ maskh, __nv_bfloat16* __restrict__ aob)
{
    extern __shared__ __nv_bfloat16 smb[];
    __nv_bfloat16* Kc = smb;
    __nv_bfloat16* Vc = smb + 352*KVS;
    __nv_bfloat16* Qc = smb + 2*352*KVS;

    const int bh = blockIdx.x;
    const int qt = blockIdx.y;
    const int b = bh / HH, h = bh - b * HH;
    const int tid = threadIdx.x, w = tid >> 5, lane = tid & 31;
    const int g = lane >> 2, tg = lane & 3;

    // ---- stage K,V (352 rows, pad >=343 with 0) ----
    const __nv_bfloat16* kbase = kb + (size_t)bh * NN * 64;
    const __nv_bfloat16* vbase = vb + (size_t)bh * NN * 64;
    for (int i = tid; i < 352*8; i += 256) {
        int row = i >> 3, cu = i & 7;
        uint4 kv = make_uint4(0,0,0,0), vv = make_uint4(0,0,0,0);
        if (row < NN) {
            kv = *(const uint4*)(kbase + (size_t)row*64 + cu*8);
            vv = *(const uint4*)(vbase + (size_t)row*64 + cu*8);
        }
        *(uint4*)(Kc + row*KVS + cu*8) = kv;
        *(uint4*)(Vc + row*KVS + cu*8) = vv;
    }
    // ---- stage Q tile ----
    const int q0 = qt * 128;
    const __nv_bfloat16* qbase = qb + (size_t)bh * NN * 64;
    for (int i = tid; i < 128*8; i += 256) {
        int row = i >> 3, cu = i & 7;
        int r = q0 + row;
        uint4 v = make_uint4(0,0,0,0);
        if (r < NN) v = *(const uint4*)(qbase + (size_t)r*64 + cu*8);
        *(uint4*)(Qc + row*KVS + cu*8) = v;
    }
    __syncthreads();

    const uint32_t kc_base = smem_u32(Kc);
    const uint32_t vc_base = smem_u32(Vc);
    const uint32_t qc_base = smem_u32(Qc);

    // ---- per-warp Q fragments: kc 0,1 = Qh; 2,3 = Ql ----
    const int a_row = lane & 15, a_koff = (lane >> 4) * 8;
    uint32_t aQ[4][4];
    #pragma unroll
    for (int kc = 0; kc < 4; kc++) {
        uint32_t addr = qc_base + ((w*16 + a_row)*KVS + kc*16 + a_koff) * 2;
        LDMATRIX_X4(aQ[kc][0], aQ[kc][1], aQ[kc][2], aQ[kc][3], addr);
    }

    const int b_l = lane & 7, b_koff = ((lane >> 3) & 1) * 8, b_nloc = (lane >> 4) * 8;
    const int v_krow = (lane & 7) + ((lane >> 3) & 1) * 8;
    const int v_noff = (lane >> 4) * 8;

    // bias row pointers (clamped for padded q rows)
    const int rg0 = q0 + w*16 + g;
    const int rg1 = rg0 + 8;
    const int rs0 = (rg0 < NN) ? rg0 : NN-1;
    const int rs1 = (rg1 < NN) ? rg1 : NN-1;
    const int wi = b & (NW-1);
    const __nv_bfloat16* rp0 = rpbh + ((size_t)h*NN + rs0) * BSTRIDE;
    const __nv_bfloat16* rp1 = rpbh + ((size_t)h*NN + rs1) * BSTRIDE;
    const __nv_bfloat16* mk0 = maskh + ((size_t)wi*NN + rs0) * BSTRIDE;
    const __nv_bfloat16* mk1 = maskh + ((size_t)wi*NN + rs1) * BSTRIDE;

    float M0 = -1e30f, M1 = -1e30f, Ssum0 = 0.f, Ssum1 = 0.f;
    float O[4][4];
    #pragma unroll
    for (int nt = 0; nt < 4; nt++)
        #pragma unroll
        for (int j = 0; j < 4; j++) O[nt][j] = 0.f;

    for (int mc = 0; mc < 22; mc++) {
        const int mbase = mc * 16;
        // K fragments (non-trans, layout [m][d] = B[n][k])
        uint32_t bK[4][4];
        #pragma unroll
        for (int kc = 0; kc < 4; kc++) {
            uint32_t addr = kc_base + ((mbase + b_nloc + b_l)*KVS + kc*16 + b_koff) * 2;
            LDMATRIX_X4(bK[kc][0], bK[kc][1], bK[kc][2], bK[kc][3], addr);
        }
        // S = Qh·Kh + Ql·Kh + Qh·Kl
        float s0[4] = {0.f,0.f,0.f,0.f}, s1[4] = {0.f,0.f,0.f,0.f};
        #pragma unroll
        for (int kc = 0; kc < 2; kc++) {
            MMA_BF16(s0[0],s0[1],s0[2],s0[3], aQ[kc][0],aQ[kc][1],aQ[kc][2],aQ[kc][3], bK[kc][0],bK[kc][1]);
            MMA_BF16(s1[0],s1[1],s1[2],s1[3], aQ[kc][0],aQ[kc][1],aQ[kc][2],aQ[kc][3], bK[kc][2],bK[kc][3]);
            MMA_BF16(s0[0],s0[1],s0[2],s0[3], aQ[kc+2][0],aQ[kc+2][1],aQ[kc+2][2],aQ[kc+2][3], bK[kc][0],bK[kc][1]);
            MMA_BF16(s1[0],s1[1],s1[2],s1[3], aQ[kc+2][0],aQ[kc+2][1],aQ[kc+2][2],aQ[kc+2][3], bK[kc][2],bK[kc][3]);
            MMA_BF16(s0[0],s0[1],s0[2],s0[3], aQ[kc][0],aQ[kc][1],aQ[kc][2],aQ[kc][3], bK[kc+2][0],bK[kc+2][1]);
            MMA_BF16(s1[0],s1[1],s1[2],s1[3], aQ[kc][0],aQ[kc][1],aQ[kc][2],aQ[kc][3], bK[kc+2][2],bK[kc+2][3]);
        }
        // bias + mask (bf16) with column bounds
        const int c0 = mbase + 2*tg;
        const int c1 = mbase + 8 + 2*tg;
        {
            __nv_bfloat162 r00 = *(const __nv_bfloat162*)(rp0 + c0);
            __nv_bfloat162 m00 = *(const __nv_bfloat162*)(mk0 + c0);
            __nv_bfloat162 r01 = *(const __nv_bfloat162*)(rp0 + c1);
            __nv_bfloat162 m01 = *(const __nv_bfloat162*)(mk0 + c1);
            __nv_bfloat162 r10 = *(const __nv_bfloat162*)(rp1 + c0);
            __nv_bfloat162 m10 = *(const __nv_bfloat162*)(mk1 + c0);
            __nv_bfloat162 r11 = *(const __nv_bfloat162*)(rp1 + c1);
            __nv_bfloat162 m11 = *(const __nv_bfloat162*)(mk1 + c1);
            s0[0] = (c0   < NN) ? s0[0] + __bfloat162float(r00.x) + __bfloat162float(m00.x) : -1e30f;
            s0[1] = (c0+1 < NN) ? s0[1] + __bfloat162float(r00.y) + __bfloat162float(m00.y) : -1e30f;
            s1[0] = (c1   < NN) ? s1[0] + __bfloat162float(r01.x) + __bfloat162float(m01.x) : -1e30f;
            s1[1] = (c1+1 < NN) ? s1[1] + __bfloat162float(r01.y) + __bfloat162float(m01.y) : -1e30f;
            s0[2] = (c0   < NN) ? s0[2] + __bfloat162float(r10.x) + __bfloat162float(m10.x) : -1e30f;
            s0[3] = (c0+1 < NN) ? s0[3] + __bfloat162float(r10.y) + __bfloat162float(m10.y) : -1e30f;
            s1[2] = (c1   < NN) ? s1[2] + __bfloat162float(r11.x) + __bfloat162float(m11.x) : -1e30f;
            s1[3] = (c1+1 < NN) ? s1[3] + __bfloat162float(r11.y) + __bfloat162float(m11.y) : -1e30f;
        }
        // online softmax update
        float cm0 = fmaxf(fmaxf(s0[0], s0[1]), fmaxf(s1[0], s1[1]));
        float cm1 = fmaxf(fmaxf(s0[2], s0[3]), fmaxf(s1[2], s1[3]));
        cm0 = fmaxf(cm0, __shfl_xor_sync(0xffffffffu, cm0, 1));
        cm0 = fmaxf(cm0, __shfl_xor_sync(0xffffffffu, cm0, 2));
        cm1 = fmaxf(cm1, __shfl_xor_sync(0xffffffffu, cm1, 1));
        cm1 = fmaxf(cm1, __shfl_xor_sync(0xffffffffu, cm1, 2));
        float Mn0 = fmaxf(M0, cm0), Mn1 = fmaxf(M1, cm1);
        float sc0 = __expf(M0 - Mn0), sc1 = __expf(M1 - Mn1);
        M0 = Mn0; M1 = Mn1;
        #pragma unroll
        for (int nt = 0; nt < 4; nt++) {
            O[nt][0] *= sc0; O[nt][1] *= sc0;
            O[nt][2] *= sc1; O[nt][3] *= sc1;
        }
        Ssum0 *= sc0; Ssum1 *= sc1;
        float p00 = __expf(s0[0]-M0), p01 = __expf(s0[1]-M0);
        float p10 = __expf(s1[0]-M0), p11 = __expf(s1[1]-M0);
        float p02 = __expf(s0[2]-M1), p03 = __expf(s0[3]-M1);
        float p12 = __expf(s1[2]-M1), p13 = __expf(s1[3]-M1);
        Ssum0 += p00 + p01 + p10 + p11;
        Ssum1 += p02 + p03 + p12 + p13;
        // P fragments (A operand), hi + lo
        float h00 = __bfloat162float(__float2bfloat16_rn(p00));
        float h01 = __bfloat162float(__float2bfloat16_rn(p01));
        float h10 = __bfloat162float(__float2bfloat16_rn(p10));
        float h11 = __bfloat162float(__float2bfloat16_rn(p11));
        float h02 = __bfloat162float(__float2bfloat16_rn(p02));
        float h03 = __bfloat162float(__float2bfloat16_rn(p03));
        float h12 = __bfloat162float(__float2bfloat16_rn(p12));
        float h13 = __bfloat162float(__float2bfloat16_rn(p13));
        uint32_t aPh[4], aPl[4];
        aPh[0] = packbf2(h00, h01); aPh[1] = packbf2(h02, h03);
        aPh[2] = packbf2(h10, h11); aPh[3] = packbf2(h12, h13);
        aPl[0] = packbf2(p00-h00, p01-h01); aPl[1] = packbf2(p02-h02, p03-h03);
        aPl[2] = packbf2(p10-h10, p11-h11); aPl[3] = packbf2(p12-h12, p13-h13);
        // V fragments (trans): q=0: Vh d0-15, q=1: Vh d16-31, q=2: Vl d0-15, q=3: Vl d16-31
        uint32_t bV[4][4];
        #pragma unroll
        for (int q = 0; q < 4; q++) {
            uint32_t addr = vc_base + ((mbase + v_krow)*KVS + q*16 + v_noff) * 2;
            LDMATRIX_X4_T(bV[q][0], bV[q][1], bV[q][2], bV[q][3], addr);
        }
        // O += Ph·Vh + Pl·Vh + Ph·Vl
        #pragma unroll
        for (int nt = 0; nt < 4; nt++) {
            uint32_t vh0 = bV[nt >> 1][(nt & 1)*2], vh1 = bV[nt >> 1][(nt & 1)*2 + 1];
            uint32_t vl0 = bV[(nt >> 1) + 2][(nt & 1)*2], vl1 = bV[(nt >> 1) + 2][(nt & 1)*2 + 1];
            MMA_BF16(O[nt][0],O[nt][1],O[nt][2],O[nt][3], aPh[0],aPh[1],aPh[2],aPh[3], vh0, vh1);
            MMA_BF16(O[nt][0],O[nt][1],O[nt][2],O[nt][3], aPl[0],aPl[1],aPl[2],aPl[3], vh0, vh1);
            MMA_BF16(O[nt][0],O[nt][1],O[nt][2],O[nt][3], aPh[0],aPh[1],aPh[2],aPh[3], vl0, vl1);
        }
    }

    // ---- finalize: row sums, divide, write bf16 hi/lo ao ----
    Ssum0 += __shfl_xor_sync(0xffffffffu, Ssum0, 1);
    Ssum0 += __shfl_xor_sync(0xffffffffu, Ssum0, 2);
    Ssum1 += __shfl_xor_sync(0xffffffffu, Ssum1, 1);
    Ssum1 += __shfl_xor_sync(0xffffffffu, Ssum1, 2);
    float inv0 = 1.f / Ssum0, inv1 = 1.f / Ssum1;

    if (rg0 < NN) {
        __nv_bfloat16* dst = aob + (size_t)(b*NN + rg0)*384 + h*32;
        #pragma unroll
        for (int nt = 0; nt < 4; nt++) {
            int dd = nt*8 + 2*tg;
            float o0 = O[nt][0]*inv0, o1 = O[nt][1]*inv0;
            __nv_bfloat16 h0 = __float2bfloat16_rn(o0);
            __nv_bfloat16 h1 = __float2bfloat16_rn(o1);
            *(__nv_bfloat162*)(dst + dd) = __nv_bfloat162(h0, h1);
            *(__nv_bfloat162*)(dst + 192 + dd) =
                __floats2bfloat162_rn(o0 - __bfloat162float(h0), o1 - __bfloat162float(h1));
        }
    }
    if (rg1 < NN) {
        __nv_bfloat16* dst = aob + (size_t)(b*NN + rg1)*384 + h*32;
        #pragma unroll
        for (int nt = 0; nt < 4; nt++) {
            int dd = nt*8 + 2*tg;
            float o0 = O[nt][2]*inv1, o1 = O[nt][3]*inv1;
            __nv_bfloat16 h0 = __float2bfloat16_rn(o0);
            __nv_bfloat16 h1 = __float2bfloat16_rn(o1);
            *(__nv_bfloat162*)(dst + dd) = __nv_bfloat162(h0, h1);
            *(__nv_bfloat162*)(dst + 192 + dd) =
                __floats2bfloat162_rn(o0 - __bfloat162float(h0), o1 - __bfloat162float(h1));
        }
    }
}

// ---------------- launch --------------------------------------------------
extern "C" void kernel_launch(void* const* d_in, const int* in_sizes, int n_in,
                              void* d_out, int out_size)
{
    const float* x_q    = (const float*)d_in[0];
    const float* x_kv   = (const float*)d_in[1];
    const float* mask   = (const float*)d_in[2];
    const float* q_w    = (const float*)d_in[3];
    const float* q_b    = (const float*)d_in[4];
    const float* kv_w   = (const float*)d_in[5];
    const float* kv_b   = (const float*)d_in[6];
    const float* proj_w = (const float*)d_in[7];
    const float* proj_b = (const float*)d_in[8];
    const float* rtab   = (const float*)d_in[9];
    const int*   rpi    = (const int*)  d_in[10];
    float* out = (float*)d_out;

    __nv_bfloat16 *xqb, *xkvb, *aob, *wc, *qbb, *kbb, *vbb, *rpbh, *maskh;
    cudaGetSymbolAddress((void**)&xqb,   g_xqb);
    cudaGetSymbolAddress((void**)&xkvb,  g_xkvb);
    cudaGetSymbolAddress((void**)&aob,   g_aob);
    cudaGetSymbolAddress((void**)&wc,    g_wcat);
    cudaGetSymbolAddress((void**)&qbb,   g_qb);
    cudaGetSymbolAddress((void**)&kbb,   g_kb);
    cudaGetSymbolAddress((void**)&vbb,   g_vb);
    cudaGetSymbolAddress((void**)&rpbh,  g_rpbh);
    cudaGetSymbolAddress((void**)&maskh, g_maskh);

    cudaFuncSetAttribute(attn_mma, cudaFuncAttributeMaxDynamicSharedMemorySize, ATTN_SMEM);

    // conversions
    aconv_kernel<<<(MM*96 + 255)/256, 256>>>(x_q,  xqb);
    aconv_kernel<<<(MM*96 + 255)/256, 256>>>(x_kv, xkvb);
    wconv_kernel<<<(768*288 + 255)/256, 256>>>(q_w, kv_w, proj_w, wc);
    rpb_gather_bf<<<(HH*NN*NN + 255)/256, 256>>>(rtab, rpi, rpbh);
    mconv_kernel<<<(NW*NN*NN + 255)/256, 256>>>(mask, maskh);
    // projections (bf16 hi/lo outputs for attention)
    gemm_mma<1><<<dim3(MM/128, 3), 256>>>(xqb, wc, q_b, nullptr, qbb, nullptr);
    gemm_mma<2><<<dim3(MM/128, 6), 256>>>(xkvb, wc + (size_t)192*576, kv_b, nullptr, kbb, vbb);
    // flash attention (HMMA)
    attn_mma<<<dim3(BB*HH, 3), 256, ATTN_SMEM>>>(qbb, kbb, vbb, rpbh, maskh, aob);
    // output projection -> d_out
    gemm_mma<0><<<dim3(MM/128, 3), 256>>>(aob, wc + (size_t)576*576, proj_b, out, nullptr, nullptr);
}

// round 12
// speedup vs baseline: 2.1646x; 1.2562x over previous
#include <cuda_runtime.h>
#include <cuda_bf16.h>
#include <cstdint>

// Problem constants
#define BB    256
#define NN    343
#define HH    6
#define DD    32
#define CC    192
#define MM    (BB*NN)      // 87808 = 686*128
#define NW    64
#define QK_SCALE 0.17677669529663687f
#define BSTRIDE 344        // padded row stride for bias tables (4B-aligned rows)

// ---------------- scratch -----------------------------------------------
__device__ __nv_bfloat16 g_xqb [MM*384];   // GEMM A: [m][hi 0..191 | lo 192..383]
__device__ __nv_bfloat16 g_xkvb[MM*384];
__device__ __nv_bfloat16 g_aob [MM*384];
__device__ __nv_bfloat16 g_wcat[768*576];  // rows: q 0..191, kv 192..575, proj 576..767
__device__ __nv_bfloat16 g_qb [BB*HH*NN*64];   // [bh][n][hi 0..31 | lo 32..63]
__device__ __nv_bfloat16 g_kb [BB*HH*NN*64];
__device__ __nv_bfloat16 g_vb [BB*HH*NN*64];
__device__ __nv_bfloat16 g_rpbh [HH*NN*BSTRIDE + 512];   // bf16 bias [h][n][344]
__device__ __nv_bfloat16 g_maskh[NW*NN*BSTRIDE + 512];   // bf16 mask [w][n][344]

__device__ __forceinline__ uint32_t smem_u32(const void* p) {
    uint32_t a;
    asm("{ .reg .u64 t; cvta.to.shared.u64 t, %1; cvt.u32.u64 %0, t; }" : "=r"(a) : "l"(p));
    return a;
}
#define LDMATRIX_X4(r0,r1,r2,r3, addr) \
    asm volatile("ldmatrix.sync.aligned.m8n8.x4.shared.b16 {%0,%1,%2,%3}, [%4];" \
        : "=r"(r0), "=r"(r1), "=r"(r2), "=r"(r3) : "r"(addr))
#define LDMATRIX_X4_T(r0,r1,r2,r3, addr) \
    asm volatile("ldmatrix.sync.aligned.m8n8.x4.trans.shared.b16 {%0,%1,%2,%3}, [%4];" \
        : "=r"(r0), "=r"(r1), "=r"(r2), "=r"(r3) : "r"(addr))
#define MMA_BF16(d0,d1,d2,d3, a0,a1,a2,a3, b0,b1) \
    asm volatile("mma.sync.aligned.m16n8k16.row.col.f32.bf16.bf16.f32 " \
        "{%0,%1,%2,%3}, {%4,%5,%6,%7}, {%8,%9}, {%0,%1,%2,%3};" \
        : "+f"(d0), "+f"(d1), "+f"(d2), "+f"(d3) \
        : "r"(a0), "r"(a1), "r"(a2), "r"(a3), "r"(b0), "r"(b1))

__device__ __forceinline__ uint32_t packbf2(float x, float y) {
    __nv_bfloat162 t = __floats2bfloat162_rn(x, y);
    return *reinterpret_cast<uint32_t*>(&t);
}

// ---------------- conversions -------------------------------------------
__global__ void aconv_kernel(const float* __restrict__ x, __nv_bfloat16* __restrict__ out)
{
    int idx = blockIdx.x * 256 + threadIdx.x;      // [0, MM*96)
    if (idx >= MM * 96) return;
    int m = idx / 96, w = idx % 96;
    float2 f = *(const float2*)(x + (size_t)m * CC + w * 2);
    __nv_bfloat16 h0 = __float2bfloat16_rn(f.x);
    __nv_bfloat16 h1 = __float2bfloat16_rn(f.y);
    __nv_bfloat162 hp(h0, h1);
    __nv_bfloat162 lp = __floats2bfloat162_rn(f.x - __bfloat162float(h0),
                                              f.y - __bfloat162float(h1));
    *(__nv_bfloat162*)(out + (size_t)m * 384 + w * 2)       = hp;
    *(__nv_bfloat162*)(out + (size_t)m * 384 + 192 + w * 2) = lp;
}

__global__ void wconv_kernel(const float* __restrict__ q_w,
                             const float* __restrict__ kv_w,
                             const float* __restrict__ proj_w,
                             __nv_bfloat16* __restrict__ wc)
{
    int idx = blockIdx.x * 256 + threadIdx.x;      // [0, 768*288)
    if (idx >= 768 * 288) return;
    int row = idx / 288, p = idx % 288;
    int kp = p * 2;
    const float* src; int r;
    if (row < 192)      { src = q_w;    r = row; }
    else if (row < 576) { src = kv_w;   r = row - 192; }
    else                { src = proj_w; r = row - 576; }
    int sc = (kp < 192) ? kp : ((kp < 384) ? kp - 192 : kp - 384);
    float f0 = src[(size_t)r * CC + sc];
    float f1 = src[(size_t)r * CC + sc + 1];
    __nv_bfloat16 h0 = __float2bfloat16_rn(f0);
    __nv_bfloat16 h1 = __float2bfloat16_rn(f1);
    __nv_bfloat162 v;
    if (kp < 384) v = __nv_bfloat162(h0, h1);
    else          v = __floats2bfloat162_rn(f0 - __bfloat162float(h0),
                                            f1 - __bfloat162float(h1));
    *(__nv_bfloat162*)(wc + (size_t)row * 576 + kp) = v;
}

// rpb gather -> bf16 [h][n][344]
__global__ void rpb_gather_bf(const float* __restrict__ table,
                              const int* __restrict__ rpi,
                              __nv_bfloat16* __restrict__ out)
{
    int idx = blockIdx.x * 256 + threadIdx.x;
    const int NM = NN * NN;
    if (idx >= HH * NM) return;
    int h = idx / NM, rem = idx - h * NM;
    int n = rem / NN, m = rem - n * NN;
    out[((size_t)h * NN + n) * BSTRIDE + m] = __float2bfloat16_rn(table[rpi[rem] * HH + h]);
}

// mask -> bf16 [w][n][344]
__global__ void mconv_kernel(const float* __restrict__ mask, __nv_bfloat16* __restrict__ out)
{
    int idx = blockIdx.x * 256 + threadIdx.x;
    const int NM = NN * NN;
    if (idx >= NW * NM) return;
    int w = idx / NM, rem = idx - w * NM;
    int n = rem / NN, m = rem - n * NN;
    out[((size_t)w * NN + n) * BSTRIDE + m] = __float2bfloat16_rn(mask[idx]);
}

// ---------------- HMMA GEMM ----------------------------------------------
// MODE 0: fp32 to C0 (proj->d_out). MODE 1: q scale -> bf16 hi/lo B0.
// MODE 2: kv split -> bf16 hi/lo B0 (k), B1 (v).
#define AS_STRIDE 72
#define BS_STRIDE 72

template <int MODE>
__global__ void __launch_bounds__(256)
gemm_mma(const __nv_bfloat16* __restrict__ gA, const __nv_bfloat16* __restrict__ gW,
         const float* __restrict__ bias, float* __restrict__ C0,
         __nv_bfloat16* __restrict__ B0, __nv_bfloat16* __restrict__ B1)
{
    __shared__ __nv_bfloat16 As[128 * AS_STRIDE];
    __shared__ __nv_bfloat16 Bs[64  * BS_STRIDE];

    const int tid = threadIdx.x, w = tid >> 5, lane = tid & 31;
    const int m0 = blockIdx.x * 128;
    const int nbase = blockIdx.y * 64;
    const int wm = (w & 3) * 32;
    const int wn = (w >> 2) * 32;

    const int a_row = lane & 15;
    const int a_koff = (lane >> 4) << 3;
    const int b_l   = lane & 7;
    const int b_koff = ((lane >> 3) & 1) * 8;
    const int b_nloc = (lane >> 4) * 8;

    float d[2][4][4];
    #pragma unroll
    for (int mt = 0; mt < 2; mt++)
        #pragma unroll
        for (int nt = 0; nt < 4; nt++)
            #pragma unroll
            for (int j = 0; j < 4; j++) d[mt][nt][j] = 0.f;

    const uint32_t as_base = smem_u32(As);
    const uint32_t bs_base = smem_u32(Bs);

    for (int it = 0; it < 9; it++) {
        const int kp0 = it * 64;
        const int acol0 = (kp0 < 384) ? kp0 : kp0 - 384;
        #pragma unroll
        for (int q = 0; q < 4; q++) {
            int f = tid + q * 256;
            int row = f >> 3, cu = f & 7;
            uint4 v = *(const uint4*)(gA + (size_t)(m0 + row) * 384 + acol0 + cu * 8);
            *(uint4*)(As + row * AS_STRIDE + cu * 8) = v;
        }
        #pragma unroll
        for (int q = 0; q < 2; q++) {
            int f = tid + q * 256;
            int row = f >> 3, cu = f & 7;
            uint4 v = *(const uint4*)(gW + (size_t)(nbase + row) * 576 + kp0 + cu * 8);
            *(uint4*)(Bs + row * BS_STRIDE + cu * 8) = v;
        }
        __syncthreads();

        #pragma unroll
        for (int ks = 0; ks < 4; ks++) {
            const int k0 = ks * 16;
            uint32_t a[2][4], bb[2][4];
            #pragma unroll
            for (int mt = 0; mt < 2; mt++) {
                uint32_t addr = as_base + ((wm + mt*16 + a_row) * AS_STRIDE + k0 + a_koff) * 2;
                LDMATRIX_X4(a[mt][0], a[mt][1], a[mt][2], a[mt][3], addr);
            }
            #pragma unroll
            for (int bt = 0; bt < 2; bt++) {
                uint32_t addr = bs_base + ((wn + bt*16 + b_nloc + b_l) * BS_STRIDE + k0 + b_koff) * 2;
                LDMATRIX_X4(bb[bt][0], bb[bt][1], bb[bt][2], bb[bt][3], addr);
            }
            #pragma unroll
            for (int mt = 0; mt < 2; mt++) {
                #pragma unroll
                for (int nt = 0; nt < 4; nt++) {
                    uint32_t b0 = bb[nt >> 1][(nt & 1) * 2];
                    uint32_t b1 = bb[nt >> 1][(nt & 1) * 2 + 1];
                    MMA_BF16(d[mt][nt][0], d[mt][nt][1], d[mt][nt][2], d[mt][nt][3],
                             a[mt][0], a[mt][1], a[mt][2], a[mt][3], b0, b1);
                }
            }
        }
        __syncthreads();
    }

    const int g = lane >> 2, tg = lane & 3;
    #pragma unroll
    for (int mt = 0; mt < 2; mt++) {
        #pragma unroll
        for (int half = 0; half < 2; half++) {
            const int m = m0 + wm + mt * 16 + g + half * 8;
            const int b_ = m / NN, nn = m - b_ * NN;
            #pragma unroll
            for (int nt = 0; nt < 4; nt++) {
                const int n = nbase + wn + nt * 8 + tg * 2;
                float v0 = d[mt][nt][half * 2 + 0] + bias[n];
                float v1 = d[mt][nt][half * 2 + 1] + bias[n + 1];
                if (MODE == 0) {
                    *(float2*)(C0 + (size_t)m * CC + n) = make_float2(v0, v1);
                } else if (MODE == 1) {
                    int h = n >> 5, dd = n & 31;
                    float s0 = v0 * QK_SCALE, s1 = v1 * QK_SCALE;
                    __nv_bfloat16 h0 = __float2bfloat16_rn(s0);
                    __nv_bfloat16 h1 = __float2bfloat16_rn(s1);
                    __nv_bfloat16* dst = B0 + (((size_t)(b_*HH + h))*NN + nn)*64 + dd;
                    *(__nv_bfloat162*)dst = __nv_bfloat162(h0, h1);
                    *(__nv_bfloat162*)(dst + 32) =
                        __floats2bfloat162_rn(s0 - __bfloat162float(h0), s1 - __bfloat162float(h1));
                } else {
                    int h = n >> 5, dd = n & 31;
                    __nv_bfloat16* dst = (h < HH)
                        ? (B0 + (((size_t)(b_*HH + h))*NN + nn)*64 + dd)
                        : (B1 + (((size_t)(b_*HH + (h - HH)))*NN + nn)*64 + dd);
                    __nv_bfloat16 h0 = __float2bfloat16_rn(v0);
                    __nv_bfloat16 h1 = __float2bfloat16_rn(v1);
                    *(__nv_bfloat162*)dst = __nv_bfloat162(h0, h1);
                    *(__nv_bfloat162*)(dst + 32) =
                        __floats2bfloat162_rn(v0 - __bfloat162float(h0), v1 - __bfloat162float(h1));
                }
            }
        }
    }
}

// ---------------- HMMA flash attention -----------------------------------
// CTA: (bh, qtile of 256 rows), 16 warps x 16 rows. K/V/Q in smem bf16 hi|lo.
// Warps whose entire 16-row strip is >= NN exit right after staging.
#define KVS 72
#define QROWS 256
#define ATTN_SMEM ((2*352*KVS + QROWS*KVS) * 2)   // 138240 B

__global__ void __launch_bounds__(512)
attn_mma(const __nv_bfloat16* __restrict__ qb, const __nv_bfloat16* __restrict__ kb,
         const __nv_bfloat16* __restrict__ vb, const __nv_bfloat16* __restrict__ rpbh,
         const __nv_bfloat16* __restrict__ maskh, __nv_bfloat16* __restrict__ aob)
{
    extern __shared__ __nv_bfloat16 smb[];
    __nv_bfloat16* Kc = smb;
    __nv_bfloat16* Vc = smb + 352*KVS;
    __nv_bfloat16* Qc = smb + 2*352*KVS;

    const int bh = blockIdx.x;
    const int qt = blockIdx.y;
    const int b = bh / HH, h = bh - b * HH;
    const int tid = threadIdx.x, w = tid >> 5, lane = tid & 31;
    const int g = lane >> 2, tg = lane & 3;

    // ---- stage K,V (352 rows, pad >=343 with 0) ----
    const __nv_bfloat16* kbase = kb + (size_t)bh * NN * 64;
    const __nv_bfloat16* vbase = vb + (size_t)bh * NN * 64;
    for (int i = tid; i < 352*8; i += 512) {
        int row = i >> 3, cu = i & 7;
        uint4 kv = make_uint4(0,0,0,0), vv = make_uint4(0,0,0,0);
        if (row < NN) {
            kv = *(const uint4*)(kbase + (size_t)row*64 + cu*8);
            vv = *(const uint4*)(vbase + (size_t)row*64 + cu*8);
        }
        *(uint4*)(Kc + row*KVS + cu*8) = kv;
        *(uint4*)(Vc + row*KVS + cu*8) = vv;
    }
    // ---- stage Q tile ----
    const int q0 = qt * QROWS;
    const __nv_bfloat16* qbase = qb + (size_t)bh * NN * 64;
    for (int i = tid; i < QROWS*8; i += 512) {
        int row = i >> 3, cu = i & 7;
        int r = q0 + row;
        uint4 v = make_uint4(0,0,0,0);
        if (r < NN) v = *(const uint4*)(qbase + (size_t)r*64 + cu*8);
        *(uint4*)(Qc + row*KVS + cu*8) = v;
    }
    __syncthreads();

    // warp-uniform early exit: this warp's 16 rows all out of range
    if (q0 + w*16 >= NN) return;

    const uint32_t kc_base = smem_u32(Kc);
    const uint32_t vc_base = smem_u32(Vc);
    const uint32_t qc_base = smem_u32(Qc);

    // ---- per-warp Q fragments: kc 0,1 = Qh; 2,3 = Ql ----
    const int a_row = lane & 15, a_koff = (lane >> 4) * 8;
    uint32_t aQ[4][4];
    #pragma unroll
    for (int kc = 0; kc < 4; kc++) {
        uint32_t addr = qc_base + ((w*16 + a_row)*KVS + kc*16 + a_koff) * 2;
        LDMATRIX_X4(aQ[kc][0], aQ[kc][1], aQ[kc][2], aQ[kc][3], addr);
    }

    const int b_l = lane & 7, b_koff = ((lane >> 3) & 1) * 8, b_nloc = (lane >> 4) * 8;
    const int v_krow = (lane & 7) + ((lane >> 3) & 1) * 8;
    const int v_noff = (lane >> 4) * 8;

    // bias row pointers (clamped for padded q rows)
    const int rg0 = q0 + w*16 + g;
    const int rg1 = rg0 + 8;
    const int rs0 = (rg0 < NN) ? rg0 : NN-1;
    const int rs1 = (rg1 < NN) ? rg1 : NN-1;
    const int wi = b & (NW-1);
    const __nv_bfloat16* rp0 = rpbh + ((size_t)h*NN + rs0) * BSTRIDE;
    const __nv_bfloat16* rp1 = rpbh + ((size_t)h*NN + rs1) * BSTRIDE;
    const __nv_bfloat16* mk0 = maskh + ((size_t)wi*NN + rs0) * BSTRIDE;
    const __nv_bfloat16* mk1 = maskh + ((size_t)wi*NN + rs1) * BSTRIDE;

    float M0 = -1e30f, M1 = -1e30f, Ssum0 = 0.f, Ssum1 = 0.f;
    float O[4][4];
    #pragma unroll
    for (int nt = 0; nt < 4; nt++)
        #pragma unroll
        for (int j = 0; j < 4; j++) O[nt][j] = 0.f;

    for (int mc = 0; mc < 22; mc++) {
        const int mbase = mc * 16;
        // K fragments (non-trans, layout [m][d] = B[n][k])
        uint32_t bK[4][4];
        #pragma unroll
        for (int kc = 0; kc < 4; kc++) {
            uint32_t addr = kc_base + ((mbase + b_nloc + b_l)*KVS + kc*16 + b_koff) * 2;
            LDMATRIX_X4(bK[kc][0], bK[kc][1], bK[kc][2], bK[kc][3], addr);
        }
        // S = Qh·Kh + Ql·Kh + Qh·Kl
        float s0[4] = {0.f,0.f,0.f,0.f}, s1[4] = {0.f,0.f,0.f,0.f};
        #pragma unroll
        for (int kc = 0; kc < 2; kc++) {
            MMA_BF16(s0[0],s0[1],s0[2],s0[3], aQ[kc][0],aQ[kc][1],aQ[kc][2],aQ[kc][3], bK[kc][0],bK[kc][1]);
            MMA_BF16(s1[0],s1[1],s1[2],s1[3], aQ[kc][0],aQ[kc][1],aQ[kc][2],aQ[kc][3], bK[kc][2],bK[kc][3]);
            MMA_BF16(s0[0],s0[1],s0[2],s0[3], aQ[kc+2][0],aQ[kc+2][1],aQ[kc+2][2],aQ[kc+2][3], bK[kc][0],bK[kc][1]);
            MMA_BF16(s1[0],s1[1],s1[2],s1[3], aQ[kc+2][0],aQ[kc+2][1],aQ[kc+2][2],aQ[kc+2][3], bK[kc][2],bK[kc][3]);
            MMA_BF16(s0[0],s0[1],s0[2],s0[3], aQ[kc][0],aQ[kc][1],aQ[kc][2],aQ[kc][3], bK[kc+2][0],bK[kc+2][1]);
            MMA_BF16(s1[0],s1[1],s1[2],s1[3], aQ[kc][0],aQ[kc][1],aQ[kc][2],aQ[kc][3], bK[kc+2][2],bK[kc+2][3]);
        }
        // bias + mask (bf16) with column bounds
        const int c0 = mbase + 2*tg;
        const int c1 = mbase + 8 + 2*tg;
        {
            __nv_bfloat162 r00 = *(const __nv_bfloat162*)(rp0 + c0);
            __nv_bfloat162 m00 = *(const __nv_bfloat162*)(mk0 + c0);
            __nv_bfloat162 r01 = *(const __nv_bfloat162*)(rp0 + c1);
            __nv_bfloat162 m01 = *(const __nv_bfloat162*)(mk0 + c1);
            __nv_bfloat162 r10 = *(const __nv_bfloat162*)(rp1 + c0);
            __nv_bfloat162 m10 = *(const __nv_bfloat162*)(mk1 + c0);
            __nv_bfloat162 r11 = *(const __nv_bfloat162*)(rp1 + c1);
            __nv_bfloat162 m11 = *(const __nv_bfloat162*)(mk1 + c1);
            s0[0] = (c0   < NN) ? s0[0] + __bfloat162float(r00.x) + __bfloat162float(m00.x) : -1e30f;
            s0[1] = (c0+1 < NN) ? s0[1] + __bfloat162float(r00.y) + __bfloat162float(m00.y) : -1e30f;
            s1[0] = (c1   < NN) ? s1[0] + __bfloat162float(r01.x) + __bfloat162float(m01.x) : -1e30f;
            s1[1] = (c1+1 < NN) ? s1[1] + __bfloat162float(r01.y) + __bfloat162float(m01.y) : -1e30f;
            s0[2] = (c0   < NN) ? s0[2] + __bfloat162float(r10.x) + __bfloat162float(m10.x) : -1e30f;
            s0[3] = (c0+1 < NN) ? s0[3] + __bfloat162float(r10.y) + __bfloat162float(m10.y) : -1e30f;
            s1[2] = (c1   < NN) ? s1[2] + __bfloat162float(r11.x) + __bfloat162float(m11.x) : -1e30f;
            s1[3] = (c1+1 < NN) ? s1[3] + __bfloat162float(r11.y) + __bfloat162float(m11.y) : -1e30f;
        }
        // online softmax update
        float cm0 = fmaxf(fmaxf(s0[0], s0[1]), fmaxf(s1[0], s1[1]));
        float cm1 = fmaxf(fmaxf(s0[2], s0[3]), fmaxf(s1[2], s1[3]));
        cm0 = fmaxf(cm0, __shfl_xor_sync(0xffffffffu, cm0, 1));
        cm0 = fmaxf(cm0, __shfl_xor_sync(0xffffffffu, cm0, 2));
        cm1 = fmaxf(cm1, __shfl_xor_sync(0xffffffffu, cm1, 1));
        cm1 = fmaxf(cm1, __shfl_xor_sync(0xffffffffu, cm1, 2));
        float Mn0 = fmaxf(M0, cm0), Mn1 = fmaxf(M1, cm1);
        float sc0 = __expf(M0 - Mn0), sc1 = __expf(M1 - Mn1);
        M0 = Mn0; M1 = Mn1;
        #pragma unroll
        for (int nt = 0; nt < 4; nt++) {
            O[nt][0] *= sc0; O[nt][1] *= sc0;
            O[nt][2] *= sc1; O[nt][3] *= sc1;
        }
        Ssum0 *= sc0; Ssum1 *= sc1;
        float p00 = __expf(s0[0]-M0), p01 = __expf(s0[1]-M0);
        float p10 = __expf(s1[0]-M0), p11 = __expf(s1[1]-M0);
        float p02 = __expf(s0[2]-M1), p03 = __expf(s0[3]-M1);
        float p12 = __expf(s1[2]-M1), p13 = __expf(s1[3]-M1);
        Ssum0 += p00 + p01 + p10 + p11;
        Ssum1 += p02 + p03 + p12 + p13;
        // P fragments (A operand), hi + lo
        float h00 = __bfloat162float(__float2bfloat16_rn(p00));
        float h01 = __bfloat162float(__float2bfloat16_rn(p01));
        float h10 = __bfloat162float(__float2bfloat16_rn(p10));
        float h11 = __bfloat162float(__float2bfloat16_rn(p11));
        float h02 = __bfloat162float(__float2bfloat16_rn(p02));
        float h03 = __bfloat162float(__float2bfloat16_rn(p03));
        float h12 = __bfloat162float(__float2bfloat16_rn(p12));
        float h13 = __bfloat162float(__float2bfloat16_rn(p13));
        uint32_t aPh[4], aPl[4];
        aPh[0] = packbf2(h00, h01); aPh[1] = packbf2(h02, h03);
        aPh[2] = packbf2(h10, h11); aPh[3] = packbf2(h12, h13);
        aPl[0] = packbf2(p00-h00, p01-h01); aPl[1] = packbf2(p02-h02, p03-h03);
        aPl[2] = packbf2(p10-h10, p11-h11); aPl[3] = packbf2(p12-h12, p13-h13);
        // V fragments (trans): q=0: Vh d0-15, q=1: Vh d16-31, q=2: Vl d0-15, q=3: Vl d16-31
        uint32_t bV[4][4];
        #pragma unroll
        for (int q = 0; q < 4; q++) {
            uint32_t addr = vc_base + ((mbase + v_krow)*KVS + q*16 + v_noff) * 2;
            LDMATRIX_X4_T(bV[q][0], bV[q][1], bV[q][2], bV[q][3], addr);
        }
        // O += Ph·Vh + Pl·Vh + Ph·Vl
        #pragma unroll
        for (int nt = 0; nt < 4; nt++) {
            uint32_t vh0 = bV[nt >> 1][(nt & 1)*2], vh1 = bV[nt >> 1][(nt & 1)*2 + 1];
            uint32_t vl0 = bV[(nt >> 1) + 2][(nt & 1)*2], vl1 = bV[(nt >> 1) + 2][(nt & 1)*2 + 1];
            MMA_BF16(O[nt][0],O[nt][1],O[nt][2],O[nt][3], aPh[0],aPh[1],aPh[2],aPh[3], vh0, vh1);
            MMA_BF16(O[nt][0],O[nt][1],O[nt][2],O[nt][3], aPl[0],aPl[1],aPl[2],aPl[3], vh0, vh1);
            MMA_BF16(O[nt][0],O[nt][1],O[nt][2],O[nt][3], aPh[0],aPh[1],aPh[2],aPh[3], vl0, vl1);
        }
    }

    // ---- finalize: row sums, divide, write bf16 hi/lo ao ----
    Ssum0 += __shfl_xor_sync(0xffffffffu, Ssum0, 1);
    Ssum0 += __shfl_xor_sync(0xffffffffu, Ssum0, 2);
    Ssum1 += __shfl_xor_sync(0xffffffffu, Ssum1, 1);
    Ssum1 += __shfl_xor_sync(0xffffffffu, Ssum1, 2);
    float inv0 = 1.f / Ssum0, inv1 = 1.f / Ssum1;

    if (rg0 < NN) {
        __nv_bfloat16* dst = aob + (size_t)(b*NN + rg0)*384 + h*32;
        #pragma unroll
        for (int nt = 0; nt < 4; nt++) {
            int dd = nt*8 + 2*tg;
            float o0 = O[nt][0]*inv0, o1 = O[nt][1]*inv0;
            __nv_bfloat16 h0 = __float2bfloat16_rn(o0);
            __nv_bfloat16 h1 = __float2bfloat16_rn(o1);
            *(__nv_bfloat162*)(dst + dd) = __nv_bfloat162(h0, h1);
            *(__nv_bfloat162*)(dst + 192 + dd) =
                __floats2bfloat162_rn(o0 - __bfloat162float(h0), o1 - __bfloat162float(h1));
        }
    }
    if (rg1 < NN) {
        __nv_bfloat16* dst = aob + (size_t)(b*NN + rg1)*384 + h*32;
        #pragma unroll
        for (int nt = 0; nt < 4; nt++) {
            int dd = nt*8 + 2*tg;
            float o0 = O[nt][2]*inv1, o1 = O[nt][3]*inv1;
            __nv_bfloat16 h0 = __float2bfloat16_rn(o0);
            __nv_bfloat16 h1 = __float2bfloat16_rn(o1);
            *(__nv_bfloat162*)(dst + dd) = __nv_bfloat162(h0, h1);
            *(__nv_bfloat162*)(dst + 192 + dd) =
                __floats2bfloat162_rn(o0 - __bfloat162float(h0), o1 - __bfloat162float(h1));
        }
    }
}

// ---------------- launch --------------------------------------------------
extern "C" void kernel_launch(void* const* d_in, const int* in_sizes, int n_in,
                              void* d_out, int out_size)
{
    const float* x_q    = (const float*)d_in[0];
    const float* x_kv   = (const float*)d_in[1];
    const float* mask   = (const float*)d_in[2];
    const float* q_w    = (const float*)d_in[3];
    const float* q_b    = (const float*)d_in[4];
    const float* kv_w   = (const float*)d_in[5];
    const float* kv_b   = (const float*)d_in[6];
    const float* proj_w = (const float*)d_in[7];
    const float* proj_b = (const float*)d_in[8];
    const float* rtab   = (const float*)d_in[9];
    const int*   rpi    = (const int*)  d_in[10];
    float* out = (float*)d_out;

    __nv_bfloat16 *xqb, *xkvb, *aob, *wc, *qbb, *kbb, *vbb, *rpbh, *maskh;
    cudaGetSymbolAddress((void**)&xqb,   g_xqb);
    cudaGetSymbolAddress((void**)&xkvb,  g_xkvb);
    cudaGetSymbolAddress((void**)&aob,   g_aob);
    cudaGetSymbolAddress((void**)&wc,    g_wcat);
    cudaGetSymbolAddress((void**)&qbb,   g_qb);
    cudaGetSymbolAddress((void**)&kbb,   g_kb);
    cudaGetSymbolAddress((void**)&vbb,   g_vb);
    cudaGetSymbolAddress((void**)&rpbh,  g_rpbh);
    cudaGetSymbolAddress((void**)&maskh, g_maskh);

    cudaFuncSetAttribute(attn_mma, cudaFuncAttributeMaxDynamicSharedMemorySize, ATTN_SMEM);

    // conversions
    aconv_kernel<<<(MM*96 + 255)/256, 256>>>(x_q,  xqb);
    aconv_kernel<<<(MM*96 + 255)/256, 256>>>(x_kv, xkvb);
    wconv_kernel<<<(768*288 + 255)/256, 256>>>(q_w, kv_w, proj_w, wc);
    rpb_gather_bf<<<(HH*NN*NN + 255)/256, 256>>>(rtab, rpi, rpbh);
    mconv_kernel<<<(NW*NN*NN + 255)/256, 256>>>(mask, maskh);
    // projections (bf16 hi/lo outputs for attention)
    gemm_mma<1><<<dim3(MM/128, 3), 256>>>(xqb, wc, q_b, nullptr, qbb, nullptr);
    gemm_mma<2><<<dim3(MM/128, 6), 256>>>(xkvb, wc + (size_t)192*576, kv_b, nullptr, kbb, vbb);
    // flash attention (HMMA, 512 threads, 2 q-tiles)
    attn_mma<<<dim3(BB*HH, 2), 512, ATTN_SMEM>>>(qbb, kbb, vbb, rpbh, maskh, aob);
    // output projection -> d_out
    gemm_mma<0><<<dim3(MM/128, 3), 256>>>(aob, wc + (size_t)576*576, proj_b, out, nullptr, nullptr);
}